// round 12
// baseline (speedup 1.0000x reference)
#include <cuda_runtime.h>
#include <math.h>

#define TDIM 1024
#define CDIM 768
#define PH 32
#define PW 32
#define NHEAD 12
#define HS 64
#define NR (8*1024)

__device__ float g_xx [NR*CDIM];
__device__ float g_xxx[NR*CDIM];
__device__ float g_t  [NR*160];
__device__ float g_xw [NR*CDIM];
__device__ float g_xk [NR*CDIM];
__device__ float g_xv [NR*CDIM];
__device__ float g_xr [NR*CDIM];
__device__ float g_xg [NR*CDIM];
__device__ float g_r  [NR*CDIM];
__device__ float g_k  [NR*CDIM];
__device__ float g_v  [NR*CDIM];
__device__ float g_g  [NR*CDIM];
__device__ float g_h1 [NR*64];
__device__ float g_w  [NR*CDIM];
__device__ float g_yg [NR*CDIM];
__device__ float g_Wc [5*CDIM*CDIM];
__device__ float g_Wt [160*CDIM + 64*CDIM + CDIM*64];
__device__ float g_Wm [5*CDIM*32];

__device__ __forceinline__ float tf32r(float x) {
    unsigned u;
    asm("cvt.rna.tf32.f32 %0, %1;" : "=r"(u) : "f"(x));
    return __uint_as_float(u);
}
__device__ __forceinline__ void cp16(void* dst, const void* src) {
    unsigned d = (unsigned)__cvta_generic_to_shared(dst);
    asm volatile("cp.async.cg.shared.global [%0], [%1], 16;" :: "r"(d), "l"(src) : "memory");
}
__device__ __forceinline__ void cp16z(void* dst, const void* src, int sz) {
    unsigned d = (unsigned)__cvta_generic_to_shared(dst);
    asm volatile("cp.async.cg.shared.global [%0], [%1], 16, %2;" :: "r"(d), "l"(src), "r"(sz) : "memory");
}

// ---------------- fused weight prep ----------------
#define NW_ (CDIM*CDIM)
#define PRE0 (5*NW_)
#define PRE1 (PRE0 + 160*CDIM)
#define PRE2 (PRE1 + 64*CDIM)
#define PRE3 (PRE2 + CDIM*64)
#define PRE4 (PRE3 + 5*CDIM*32)
__global__ void prep_all_kernel(const float* __restrict__ w0, const float* __restrict__ w1,
                                const float* __restrict__ w2, const float* __restrict__ w3,
                                const float* __restrict__ w4,
                                const float* __restrict__ maa_w1, const float* __restrict__ dec_w1,
                                const float* __restrict__ dec_w2, const float* __restrict__ maa_w2,
                                float* __restrict__ Wc, float* __restrict__ Wt, float* __restrict__ Wm)
{
    int idx = blockIdx.x * blockDim.x + threadIdx.x;
    if (idx >= PRE4) return;
    if (idx < PRE0) {
        int m = idx / NW_, r = idx % NW_;
        const float* src = (m == 0) ? w0 : (m == 1) ? w1 : (m == 2) ? w2 : (m == 3) ? w3 : w4;
        Wc[idx] = tf32r(src[r]);
    } else if (idx < PRE1) {
        int o = idx - PRE0;
        int n = o / CDIM, k = o % CDIM;
        Wt[o] = tf32r(maa_w1[k * 160 + n]);
    } else if (idx < PRE2) {
        int o = idx - PRE1;
        int n = o / CDIM, k = o % CDIM;
        Wt[160 * CDIM + o] = tf32r(dec_w1[k * 64 + n]);
    } else if (idx < PRE3) {
        int o = idx - PRE2;
        int n = o / 64, k = o % 64;
        Wt[160 * CDIM + 64 * CDIM + o] = tf32r(dec_w2[k * CDIM + n]);
    } else {
        int o = idx - PRE3;
        int f = o / (CDIM * 32);
        int rem = o % (CDIM * 32);
        int c = rem >> 5, j = rem & 31;
        Wm[o] = tf32r(maa_w2[(f * 32 + j) * CDIM + c]);
    }
}

// ---------------- K1: q_shift + maa_x mix (float4) ----------------
#define C4 (CDIM/4)
__global__ void shift_mix_kernel(const float* __restrict__ x,
                                 const float* __restrict__ maa_x,
                                 float* __restrict__ xx, float* __restrict__ xxx,
                                 int total4)
{
    int idx = blockIdx.x * blockDim.x + threadIdx.x;
    if (idx >= total4) return;
    int c4 = idx % C4;
    int t = (idx / C4) % TDIM;
    int b = idx / (C4 * TDIM);
    int d4 = c4 & 15;
    int hh = t >> 5, ww = t & 31;
    int st = -1;
    if (d4 < 4)       { if (ww >= 1)      st = t - 1;  }
    else if (d4 < 8)  { if (ww < PW - 1)  st = t + 1;  }
    else if (d4 < 12) { if (hh >= 1)      st = t - PW; }
    else              { if (hh < PH - 1)  st = t + PW; }
    float4 sh = make_float4(0.f, 0.f, 0.f, 0.f);
    if (st >= 0)
        sh = *(const float4*)(x + (((size_t)b * TDIM + st) * C4 + c4) * 4);
    float4 xv = *(const float4*)(x + (size_t)idx * 4);
    float4 mm = *(const float4*)(maa_x + c4 * 4);
    float4 dd, ox;
    dd.x = sh.x - xv.x; dd.y = sh.y - xv.y; dd.z = sh.z - xv.z; dd.w = sh.w - xv.w;
    ox.x = tf32r(xv.x + dd.x * mm.x);
    ox.y = tf32r(xv.y + dd.y * mm.y);
    ox.z = tf32r(xv.z + dd.z * mm.z);
    ox.w = tf32r(xv.w + dd.w * mm.w);
    *(float4*)(xx + (size_t)idx * 4) = dd;
    *(float4*)(xxx + (size_t)idx * 4) = ox;
}

// ---------------- mma.sync tf32 GEMM (2-stage, proven) ----------------
#define ASTR   36
#define ASZ    (128*ASTR)
#define GT_SMEM (4*ASZ*4)   // 73728 B

template<int EPI>
__device__ __forceinline__ float epi_f(float a, const float* bias, int n) {
    if (EPI == 1) return tanhf(a);
    if (EPI == 2) return fmaxf(a, 0.f);
    if (EPI == 3) return a + bias[n];
    if (EPI == 4) return tf32r(tanhf(a));
    return a;
}

__device__ __forceinline__ void gt_issue(float* sm, const float* __restrict__ A,
                                         const float* __restrict__ Bm,
                                         int m0, int n0, int it, int tid, int N, int K)
{
    int s = it & 1;
    float* As = sm + s * ASZ;
    float* Bs = sm + 2 * ASZ + s * ASZ;
    int k0 = it * 32;
#pragma unroll
    for (int p = 0; p < 4; p++) {
        int c = tid + p * 256;
        int row = c >> 3, kc = (c & 7) << 2;
        cp16(As + row * ASTR + kc, A + (size_t)(m0 + row) * K + k0 + kc);
    }
#pragma unroll
    for (int p = 0; p < 4; p++) {
        int c = tid + p * 256;
        int row = c >> 3, kc = (c & 7) << 2;
        int valid = (n0 + row) < N;
        const float* src = Bm + (valid ? ((size_t)(n0 + row) * K + k0 + kc) : 0);
        cp16z(Bs + row * ASTR + kc, src, valid ? 16 : 0);
    }
    asm volatile("cp.async.commit_group;" ::: "memory");
}

__device__ __forceinline__ void gt_mma_stage(const float* As, const float* Bs,
                                             int warp_m, int warp_n, int lane,
                                             float acc[4][4][4])
{
    int lrow = lane & 7;
    int a_m = ((lane >> 3) & 1) * 8 + lrow;
    int a_k = (lane >> 4) * 4;
    int b_row8 = ((lane >> 4) & 1) * 8 + lrow;
    int b_k = ((lane >> 3) & 1) * 4;
#pragma unroll
    for (int ks = 0; ks < 4; ks++) {
        unsigned af[4][4], bf[4][2];
#pragma unroll
        for (int mi = 0; mi < 4; mi++) {
            const float* p = As + (warp_m * 64 + mi * 16 + a_m) * ASTR + ks * 8 + a_k;
            unsigned ad = (unsigned)__cvta_generic_to_shared(p);
            asm volatile("ldmatrix.sync.aligned.m8n8.x4.shared.b16 {%0,%1,%2,%3}, [%4];"
                : "=r"(af[mi][0]), "=r"(af[mi][1]), "=r"(af[mi][2]), "=r"(af[mi][3]) : "r"(ad));
        }
#pragma unroll
        for (int np = 0; np < 2; np++) {
            const float* p = Bs + (warp_n * 32 + np * 16 + b_row8) * ASTR + ks * 8 + b_k;
            unsigned ad = (unsigned)__cvta_generic_to_shared(p);
            asm volatile("ldmatrix.sync.aligned.m8n8.x4.shared.b16 {%0,%1,%2,%3}, [%4];"
                : "=r"(bf[np * 2][0]), "=r"(bf[np * 2][1]),
                  "=r"(bf[np * 2 + 1][0]), "=r"(bf[np * 2 + 1][1]) : "r"(ad));
        }
#pragma unroll
        for (int mi = 0; mi < 4; mi++)
#pragma unroll
            for (int ni = 0; ni < 4; ni++) {
                asm volatile(
                    "mma.sync.aligned.m16n8k8.row.col.f32.tf32.tf32.f32 "
                    "{%0,%1,%2,%3}, {%4,%5,%6,%7}, {%8,%9}, {%0,%1,%2,%3};"
                    : "+f"(acc[mi][ni][0]), "+f"(acc[mi][ni][1]),
                      "+f"(acc[mi][ni][2]), "+f"(acc[mi][ni][3])
                    : "r"(af[mi][0]), "r"(af[mi][1]), "r"(af[mi][2]), "r"(af[mi][3]),
                      "r"(bf[ni][0]), "r"(bf[ni][1]));
            }
    }
}

template<int EPI, bool RELU_RT>
__device__ __forceinline__ void gt_body(const float* __restrict__ A, const float* __restrict__ Bm,
                                        float* __restrict__ Cm, int N, int K,
                                        const float* __restrict__ bias, int relu_flag)
{
    extern __shared__ __align__(16) float sm[];
    int tid = threadIdx.x;
    int lane = tid & 31, warp = tid >> 5;
    int warp_m = warp >> 2, warp_n = warp & 3;
    int m0 = blockIdx.y * 128, n0 = blockIdx.x * 128;

    float acc[4][4][4];
#pragma unroll
    for (int i = 0; i < 4; i++)
#pragma unroll
        for (int j = 0; j < 4; j++)
#pragma unroll
            for (int q = 0; q < 4; q++) acc[i][j][q] = 0.f;

    gt_issue(sm, A, Bm, m0, n0, 0, tid, N, K);

    const int NIT = K / 32;
#pragma unroll 1
    for (int it = 0; it < NIT; it++) {
        if (it + 1 < NIT) {
            gt_issue(sm, A, Bm, m0, n0, it + 1, tid, N, K);
            asm volatile("cp.async.wait_group 1;" ::: "memory");
        } else {
            asm volatile("cp.async.wait_group 0;" ::: "memory");
        }
        __syncthreads();
        int s = it & 1;
        gt_mma_stage(sm + s * ASZ, sm + 2 * ASZ + s * ASZ, warp_m, warp_n, lane, acc);
        __syncthreads();
    }

    int erow = lane >> 2, ecol = (lane & 3) * 2;
#pragma unroll
    for (int mi = 0; mi < 4; mi++) {
#pragma unroll
        for (int ni = 0; ni < 4; ni++) {
            int m = m0 + warp_m * 64 + mi * 16 + erow;
            int n = n0 + warp_n * 32 + ni * 8 + ecol;
            if (n < N) {
                float2 v0, v1;
                v0.x = epi_f<EPI>(acc[mi][ni][0], bias, n);
                v0.y = epi_f<EPI>(acc[mi][ni][1], bias, n + 1);
                v1.x = epi_f<EPI>(acc[mi][ni][2], bias, n);
                v1.y = epi_f<EPI>(acc[mi][ni][3], bias, n + 1);
                if (RELU_RT && relu_flag) {
                    v0.x = fmaxf(v0.x, 0.f); v0.y = fmaxf(v0.y, 0.f);
                    v1.x = fmaxf(v1.x, 0.f); v1.y = fmaxf(v1.y, 0.f);
                }
                *(float2*)(Cm + (size_t)m * N + n) = v0;
                *(float2*)(Cm + (size_t)(m + 8) * N + n) = v1;
            }
        }
    }
}

template<int EPI>
__global__ __launch_bounds__(256, 2) void gemm_tf32_kernel(
    const float* __restrict__ A, const float* __restrict__ Bm,
    float* __restrict__ Cm, int N, int K, const float* __restrict__ bias)
{
    gt_body<EPI, false>(A, Bm, Cm, N, K, bias, 0);
}

__global__ __launch_bounds__(256, 2) void gemm_tf32_batch5_kernel(
    const float* __restrict__ a0, const float* __restrict__ a1,
    const float* __restrict__ a2, const float* __restrict__ a3,
    const float* __restrict__ a4,
    const float* __restrict__ b0, const float* __restrict__ b1,
    const float* __restrict__ b2, const float* __restrict__ b3,
    const float* __restrict__ b4,
    float* __restrict__ c0, float* __restrict__ c1,
    float* __restrict__ c2, float* __restrict__ c3,
    float* __restrict__ c4,
    const float* __restrict__ bias4)
{
    int z = blockIdx.z;
    if (z < 4) {
        const float* A  = (z == 0) ? a0 : (z == 1) ? a1 : (z == 2) ? a2 : a3;
        const float* Bm = (z == 0) ? b0 : (z == 1) ? b1 : (z == 2) ? b2 : b3;
        float* Cm       = (z == 0) ? c0 : (z == 1) ? c1 : (z == 2) ? c2 : c3;
        gt_body<0, true>(A, Bm, Cm, CDIM, CDIM, nullptr, z == 3);
    } else {
        gt_body<3, false>(a4, b4, c4, CDIM, 64, bias4, 0);
    }
}

// ---------------- mix5 GEMM, 128x64 tile, smem-cached x/xx ----------------
#define M5_XS 0
#define M5_DS 9216
#define M5_AS 18432
#define M5_BS 23040
#define M5_SMEM (25344*4)

__global__ __launch_bounds__(256, 2) void mix5g_kernel(
    const float* __restrict__ tb, const float* __restrict__ Wm,
    const float* __restrict__ x, const float* __restrict__ xx,
    const float* __restrict__ mw, const float* __restrict__ mk,
    const float* __restrict__ mv, const float* __restrict__ mr,
    const float* __restrict__ mg,
    float* __restrict__ xw, float* __restrict__ xk, float* __restrict__ xv,
    float* __restrict__ xr, float* __restrict__ xg)
{
    extern __shared__ __align__(16) float sm[];
    int tid = threadIdx.x;
    int lane = tid & 31, warp = tid >> 5;
    int warp_m = warp >> 1, warp_n = warp & 1;
    int m0 = blockIdx.y * 128, n0 = blockIdx.x * 64;
    int erow = lane >> 2, ecol = (lane & 3) * 2;

#pragma unroll
    for (int p = 0; p < 8; p++) {
        int c = tid + p * 256;
        int row = c >> 4, c16 = c & 15;
        cp16(sm + M5_XS + row * 72 + c16 * 4, x  + (size_t)(m0 + row) * CDIM + n0 + c16 * 4);
        cp16(sm + M5_DS + row * 72 + c16 * 4, xx + (size_t)(m0 + row) * CDIM + n0 + c16 * 4);
    }
    asm volatile("cp.async.commit_group;" ::: "memory");

#pragma unroll 1
    for (int f = 0; f < 5; f++) {
#pragma unroll
        for (int p = 0; p < 4; p++) {
            int c = tid + p * 256;
            int row = c >> 3, kc = (c & 7) << 2;
            cp16(sm + M5_AS + row * ASTR + kc, tb + (size_t)(m0 + row) * 160 + f * 32 + kc);
        }
#pragma unroll
        for (int p = 0; p < 2; p++) {
            int c = tid + p * 256;
            int row = c >> 3, kc = (c & 7) << 2;
            cp16(sm + M5_BS + row * ASTR + kc, Wm + (size_t)f * CDIM * 32 + (size_t)(n0 + row) * 32 + kc);
        }
        asm volatile("cp.async.commit_group;" ::: "memory");
        asm volatile("cp.async.wait_group 0;" ::: "memory");
        __syncthreads();

        float acc[2][4][4];
#pragma unroll
        for (int i = 0; i < 2; i++)
#pragma unroll
            for (int j = 0; j < 4; j++)
#pragma unroll
                for (int q = 0; q < 4; q++) acc[i][j][q] = 0.f;

        {
            const float* As = sm + M5_AS;
            const float* Bs = sm + M5_BS;
            int lrow = lane & 7;
            int a_m = ((lane >> 3) & 1) * 8 + lrow;
            int a_k = (lane >> 4) * 4;
            int b_row8 = ((lane >> 4) & 1) * 8 + lrow;
            int b_k = ((lane >> 3) & 1) * 4;
#pragma unroll
            for (int ks = 0; ks < 4; ks++) {
                unsigned af[2][4], bf[4][2];
#pragma unroll
                for (int mi = 0; mi < 2; mi++) {
                    const float* p = As + (warp_m * 32 + mi * 16 + a_m) * ASTR + ks * 8 + a_k;
                    unsigned ad = (unsigned)__cvta_generic_to_shared(p);
                    asm volatile("ldmatrix.sync.aligned.m8n8.x4.shared.b16 {%0,%1,%2,%3}, [%4];"
                        : "=r"(af[mi][0]), "=r"(af[mi][1]), "=r"(af[mi][2]), "=r"(af[mi][3]) : "r"(ad));
                }
#pragma unroll
                for (int np = 0; np < 2; np++) {
                    const float* p = Bs + (warp_n * 32 + np * 16 + b_row8) * ASTR + ks * 8 + b_k;
                    unsigned ad = (unsigned)__cvta_generic_to_shared(p);
                    asm volatile("ldmatrix.sync.aligned.m8n8.x4.shared.b16 {%0,%1,%2,%3}, [%4];"
                        : "=r"(bf[np * 2][0]), "=r"(bf[np * 2][1]),
                          "=r"(bf[np * 2 + 1][0]), "=r"(bf[np * 2 + 1][1]) : "r"(ad));
                }
#pragma unroll
                for (int mi = 0; mi < 2; mi++)
#pragma unroll
                    for (int ni = 0; ni < 4; ni++) {
                        asm volatile(
                            "mma.sync.aligned.m16n8k8.row.col.f32.tf32.tf32.f32 "
                            "{%0,%1,%2,%3}, {%4,%5,%6,%7}, {%8,%9}, {%0,%1,%2,%3};"
                            : "+f"(acc[mi][ni][0]), "+f"(acc[mi][ni][1]),
                              "+f"(acc[mi][ni][2]), "+f"(acc[mi][ni][3])
                            : "r"(af[mi][0]), "r"(af[mi][1]), "r"(af[mi][2]), "r"(af[mi][3]),
                              "r"(bf[ni][0]), "r"(bf[ni][1]));
                    }
            }
        }

        const float* maa_f = (f == 0) ? mw : (f == 1) ? mk : (f == 2) ? mv : (f == 3) ? mr : mg;
        float* out_f       = (f == 0) ? xw : (f == 1) ? xk : (f == 2) ? xv : (f == 3) ? xr : xg;
#pragma unroll
        for (int mi = 0; mi < 2; mi++) {
#pragma unroll
            for (int ni = 0; ni < 4; ni++) {
                int ml = warp_m * 32 + mi * 16 + erow;
                int nl = warp_n * 32 + ni * 8 + ecol;
                int ng = n0 + nl;
                float2 xa = *(const float2*)(sm + M5_XS + ml * 72 + nl);
                float2 xb = *(const float2*)(sm + M5_XS + (ml + 8) * 72 + nl);
                float2 da = *(const float2*)(sm + M5_DS + ml * 72 + nl);
                float2 db = *(const float2*)(sm + M5_DS + (ml + 8) * 72 + nl);
                float2 ma = *(const float2*)(maa_f + ng);
                float2 v0, v1;
                v0.x = tf32r(xa.x + da.x * (ma.x + acc[mi][ni][0]));
                v0.y = tf32r(xa.y + da.y * (ma.y + acc[mi][ni][1]));
                v1.x = tf32r(xb.x + db.x * (ma.x + acc[mi][ni][2]));
                v1.y = tf32r(xb.y + db.y * (ma.y + acc[mi][ni][3]));
                *(float2*)(out_f + (size_t)(m0 + ml) * CDIM + ng) = v0;
                *(float2*)(out_f + (size_t)(m0 + ml + 8) * CDIM + ng) = v1;
            }
        }
        __syncthreads();
    }
}

// ---------------- K4: WKV6 recurrence + fused GroupNorm*g ----------------
__device__ __forceinline__ void wkv_issue(int ci, float* rsb, float* ksb,
        float* vsb, float* wsb,
        const float* rp, const float* kp, const float* vp, const float* wpp,
        size_t base, int tid)
{
#pragma unroll
    for (int p = 0; p < 2; p++) {
        int idx = tid + p * 256;
        int arr = idx >> 7;
        int rem = idx & 127;
        int tc = rem >> 4, c4 = (rem & 15) << 2;
        size_t gofs = base + (size_t)(ci * 8 + tc) * CDIM + c4;
        float* dst; const float* src;
        if (arr == 0)      { dst = rsb + tc * 64 + c4; src = rp  + gofs; }
        else if (arr == 1) { dst = ksb + tc * 64 + c4; src = kp  + gofs; }
        else if (arr == 2) { dst = vsb + tc * 64 + c4; src = vp  + gofs; }
        else               { dst = wsb + tc * 64 + c4; src = wpp + gofs; }
        cp16(dst, src);
    }
    asm volatile("cp.async.commit_group;" ::: "memory");
}

__global__ __launch_bounds__(256, 1) void wkv6_kernel(
    const float* __restrict__ rp, const float* __restrict__ kp,
    const float* __restrict__ vp, const float* __restrict__ wp_,
    const float* __restrict__ up,
    const float* __restrict__ gp,
    const float* __restrict__ lw, const float* __restrict__ lb,
    float* __restrict__ yg)
{
    __shared__ __align__(16) float rs[2][512], ks[2][512], vs[2][512], ws[2][512];
    __shared__ float us[64], ruks[8], ys[8 * 72];
    int tid = threadIdx.x;
    int b = blockIdx.x / NHEAD, h = blockIdx.x % NHEAD;
    size_t base = (size_t)b * TDIM * CDIM + h * HS;
    if (tid < 64) us[tid] = up[h * HS + tid];
    int i = tid >> 2, jq = tid & 3;
    int lane = tid & 31, warp = tid >> 5;

    float lw0 = lw[h * HS + lane],      lw1 = lw[h * HS + 32 + lane];
    float lb0 = lb[h * HS + lane],      lb1 = lb[h * HS + 32 + lane];

    float S[16];
#pragma unroll
    for (int q = 0; q < 16; q++) S[q] = 0.f;

    wkv_issue(0, rs[0], ks[0], vs[0], ws[0], rp, kp, vp, wp_, base, tid);

#pragma unroll 1
    for (int ci = 0; ci < TDIM / 8; ci++) {
        int buf = ci & 1;
        asm volatile("cp.async.wait_group 0;" ::: "memory");
        __syncthreads();
        for (int idx = tid; idx < 512; idx += 256)
            ws[buf][idx] = expf(-expf(ws[buf][idx]));
        {
            float p = rs[buf][warp * 64 + lane] * us[lane] * ks[buf][warp * 64 + lane]
                    + rs[buf][warp * 64 + 32 + lane] * us[32 + lane] * ks[buf][warp * 64 + 32 + lane];
#pragma unroll
            for (int o = 16; o; o >>= 1) p += __shfl_xor_sync(0xffffffffu, p, o);
            if (lane == 0) ruks[warp] = p;
        }
        __syncthreads();
        if (ci + 1 < TDIM / 8) {
            int nb = buf ^ 1;
            wkv_issue(ci + 1, rs[nb], ks[nb], vs[nb], ws[nb], rp, kp, vp, wp_, base, tid);
        }
#pragma unroll 1
        for (int tc = 0; tc < 8; tc++) {
            float vi = vs[buf][tc * 64 + i];
            const float4* r4 = (const float4*)&rs[buf][tc * 64 + jq * 16];
            const float4* k4 = (const float4*)&ks[buf][tc * 64 + jq * 16];
            const float4* w4 = (const float4*)&ws[buf][tc * 64 + jq * 16];
            float yps = 0.f;
#pragma unroll
            for (int q = 0; q < 4; q++) {
                float4 rv = r4[q], kv = k4[q], wv = w4[q];
                yps += rv.x * S[q * 4 + 0]; S[q * 4 + 0] = wv.x * S[q * 4 + 0] + kv.x * vi;
                yps += rv.y * S[q * 4 + 1]; S[q * 4 + 1] = wv.y * S[q * 4 + 1] + kv.y * vi;
                yps += rv.z * S[q * 4 + 2]; S[q * 4 + 2] = wv.z * S[q * 4 + 2] + kv.z * vi;
                yps += rv.w * S[q * 4 + 3]; S[q * 4 + 3] = wv.w * S[q * 4 + 3] + kv.w * vi;
            }
            yps += __shfl_xor_sync(0xffffffffu, yps, 1);
            yps += __shfl_xor_sync(0xffffffffu, yps, 2);
            if (jq == 0)
                ys[tc * 72 + i] = yps + vi * ruks[tc];
        }
        __syncthreads();
        {
            int trow = ci * 8 + warp;
            float v0 = ys[warp * 72 + lane], v1 = ys[warp * 72 + 32 + lane];
            float s = v0 + v1, ss = v0 * v0 + v1 * v1;
#pragma unroll
            for (int off = 16; off; off >>= 1) {
                s  += __shfl_xor_sync(0xffffffffu, s,  off);
                ss += __shfl_xor_sync(0xffffffffu, ss, off);
            }
            float mean = s * (1.f / HS);
            float var  = ss * (1.f / HS) - mean * mean;
            float inv  = rsqrtf(var + 1e-5f);
            size_t o = base + (size_t)trow * CDIM;
            float n0v = (v0 - mean) * inv * lw0 + lb0;
            float n1v = (v1 - mean) * inv * lw1 + lb1;
            yg[o + lane]      = tf32r(n0v * gp[o + lane]);
            yg[o + 32 + lane] = tf32r(n1v * gp[o + 32 + lane]);
        }
    }
}

// ---------------- launcher ----------------
extern "C" void kernel_launch(void* const* d_in, const int* in_sizes, int n_in,
                              void* d_out, int out_size)
{
    const float* x          = (const float*)d_in[0];
    const float* W_r        = (const float*)d_in[1];
    const float* W_k        = (const float*)d_in[2];
    const float* W_v        = (const float*)d_in[3];
    const float* W_g        = (const float*)d_in[4];
    const float* W_o        = (const float*)d_in[5];
    const float* maa_x      = (const float*)d_in[6];
    const float* maa_w      = (const float*)d_in[7];
    const float* maa_k      = (const float*)d_in[8];
    const float* maa_v      = (const float*)d_in[9];
    const float* maa_r      = (const float*)d_in[10];
    const float* maa_g      = (const float*)d_in[11];
    const float* maa_w1     = (const float*)d_in[12];
    const float* maa_w2     = (const float*)d_in[13];
    const float* time_decay = (const float*)d_in[14];
    const float* dec_w1     = (const float*)d_in[15];
    const float* dec_w2     = (const float*)d_in[16];
    const float* faaaa      = (const float*)d_in[17];
    const float* ln_w       = (const float*)d_in[18];
    const float* ln_b       = (const float*)d_in[19];
    float* out = (float*)d_out;

    float *xx, *xxx, *tb, *xw, *xk, *xv, *xr, *xg, *rb, *kb, *vb, *gb, *h1, *wb, *yg, *Wc, *Wt, *Wm;
    cudaGetSymbolAddress((void**)&xx,  g_xx);
    cudaGetSymbolAddress((void**)&xxx, g_xxx);
    cudaGetSymbolAddress((void**)&tb,  g_t);
    cudaGetSymbolAddress((void**)&xw,  g_xw);
    cudaGetSymbolAddress((void**)&xk,  g_xk);
    cudaGetSymbolAddress((void**)&xv,  g_xv);
    cudaGetSymbolAddress((void**)&xr,  g_xr);
    cudaGetSymbolAddress((void**)&xg,  g_xg);
    cudaGetSymbolAddress((void**)&rb,  g_r);
    cudaGetSymbolAddress((void**)&kb,  g_k);
    cudaGetSymbolAddress((void**)&vb,  g_v);
    cudaGetSymbolAddress((void**)&gb,  g_g);
    cudaGetSymbolAddress((void**)&h1,  g_h1);
    cudaGetSymbolAddress((void**)&wb,  g_w);
    cudaGetSymbolAddress((void**)&yg,  g_yg);
    cudaGetSymbolAddress((void**)&Wc,  g_Wc);
    cudaGetSymbolAddress((void**)&Wt,  g_Wt);
    cudaGetSymbolAddress((void**)&Wm,  g_Wm);

    const int NW = CDIM * CDIM;
    float* Wr_c = Wc + 0 * NW;
    float* Wk_c = Wc + 1 * NW;
    float* Wv_c = Wc + 2 * NW;
    float* Wg_c = Wc + 3 * NW;
    float* Wo_c = Wc + 4 * NW;
    float* W1t  = Wt;
    float* D1t  = Wt + 160 * CDIM;
    float* D2t  = Wt + 160 * CDIM + 64 * CDIM;

    cudaFuncSetAttribute(gemm_tf32_kernel<0>, cudaFuncAttributeMaxDynamicSharedMemorySize, GT_SMEM);
    cudaFuncSetAttribute(gemm_tf32_kernel<4>, cudaFuncAttributeMaxDynamicSharedMemorySize, GT_SMEM);
    cudaFuncSetAttribute(gemm_tf32_batch5_kernel, cudaFuncAttributeMaxDynamicSharedMemorySize, GT_SMEM);
    cudaFuncSetAttribute(mix5g_kernel, cudaFuncAttributeMaxDynamicSharedMemorySize, M5_SMEM);

    int total4 = NR * C4;

    prep_all_kernel<<<(PRE4 + 255) / 256, 256>>>(W_r, W_k, W_v, W_g, W_o,            // 1
        maa_w1, dec_w1, dec_w2, maa_w2, Wc, Wt, Wm);
    shift_mix_kernel<<<(total4 + 255) / 256, 256>>>(x, maa_x, xx, xxx, total4);      // 2
    {                                                                                 // 3
        dim3 grid(2, NR / 128);
        gemm_tf32_kernel<4><<<grid, 256, GT_SMEM>>>(xxx, W1t, tb, 160, CDIM, nullptr);
    }
    {                                                                                 // 4 <- profiled
        dim3 grid(CDIM / 64, NR / 128);
        mix5g_kernel<<<grid, 256, M5_SMEM>>>(tb, Wm, x, xx,
            maa_w, maa_k, maa_v, maa_r, maa_g, xw, xk, xv, xr, xg);
    }
    {                                                                                 // 5
        dim3 grid(1, NR / 128);
        gemm_tf32_kernel<4><<<grid, 256, GT_SMEM>>>(xw, D1t, h1, 64, CDIM, nullptr);
    }
    {                                                                                 // 6
        dim3 grid(6, NR / 128, 5);
        gemm_tf32_batch5_kernel<<<grid, 256, GT_SMEM>>>(
            xr, xk, xv, xg, h1, Wr_c, Wk_c, Wv_c, Wg_c, D2t,
            rb, kb, vb, gb, wb, time_decay);
    }
    wkv6_kernel<<<8 * NHEAD, 256>>>(rb, kb, vb, wb, faaaa, gb, ln_w, ln_b, yg);       // 7
    {                                                                                 // 8
        dim3 gcc(6, NR / 128);
        gemm_tf32_kernel<0><<<gcc, 256, GT_SMEM>>>(yg, Wo_c, out, CDIM, CDIM, nullptr);
    }
}

// round 13
// speedup vs baseline: 1.0365x; 1.0365x over previous
#include <cuda_runtime.h>
#include <math.h>

#define TDIM 1024
#define CDIM 768
#define PH 32
#define PW 32
#define NHEAD 12
#define HS 64
#define NR (8*1024)

__device__ float g_xx [NR*CDIM];
__device__ float g_xxx[NR*CDIM];
__device__ float g_t  [NR*160];
__device__ float g_xw [NR*CDIM];
__device__ float g_xk [NR*CDIM];
__device__ float g_xv [NR*CDIM];
__device__ float g_xr [NR*CDIM];
__device__ float g_xg [NR*CDIM];
__device__ float g_r  [NR*CDIM];
__device__ float g_k  [NR*CDIM];
__device__ float g_v  [NR*CDIM];
__device__ float g_g  [NR*CDIM];
__device__ float g_h1 [NR*64];
__device__ float g_w  [NR*CDIM];
__device__ float g_y  [NR*CDIM];
__device__ float g_yg [NR*CDIM];
__device__ float g_Wc [5*CDIM*CDIM];
__device__ float g_Wt [160*CDIM + 64*CDIM + CDIM*64];
__device__ float g_Wm [5*CDIM*32];

__device__ __forceinline__ float tf32r(float x) {
    unsigned u;
    asm("cvt.rna.tf32.f32 %0, %1;" : "=r"(u) : "f"(x));
    return __uint_as_float(u);
}
__device__ __forceinline__ void cp16(void* dst, const void* src) {
    unsigned d = (unsigned)__cvta_generic_to_shared(dst);
    asm volatile("cp.async.cg.shared.global [%0], [%1], 16;" :: "r"(d), "l"(src) : "memory");
}
__device__ __forceinline__ void cp16z(void* dst, const void* src, int sz) {
    unsigned d = (unsigned)__cvta_generic_to_shared(dst);
    asm volatile("cp.async.cg.shared.global [%0], [%1], 16, %2;" :: "r"(d), "l"(src), "r"(sz) : "memory");
}

// ---------------- fused weight prep ----------------
#define NW_ (CDIM*CDIM)
#define PRE0 (5*NW_)
#define PRE1 (PRE0 + 160*CDIM)
#define PRE2 (PRE1 + 64*CDIM)
#define PRE3 (PRE2 + CDIM*64)
#define PRE4 (PRE3 + 5*CDIM*32)
__global__ void prep_all_kernel(const float* __restrict__ w0, const float* __restrict__ w1,
                                const float* __restrict__ w2, const float* __restrict__ w3,
                                const float* __restrict__ w4,
                                const float* __restrict__ maa_w1, const float* __restrict__ dec_w1,
                                const float* __restrict__ dec_w2, const float* __restrict__ maa_w2,
                                float* __restrict__ Wc, float* __restrict__ Wt, float* __restrict__ Wm)
{
    int idx = blockIdx.x * blockDim.x + threadIdx.x;
    if (idx >= PRE4) return;
    if (idx < PRE0) {
        int m = idx / NW_, r = idx % NW_;
        const float* src = (m == 0) ? w0 : (m == 1) ? w1 : (m == 2) ? w2 : (m == 3) ? w3 : w4;
        Wc[idx] = tf32r(src[r]);
    } else if (idx < PRE1) {
        int o = idx - PRE0;
        int n = o / CDIM, k = o % CDIM;
        Wt[o] = tf32r(maa_w1[k * 160 + n]);
    } else if (idx < PRE2) {
        int o = idx - PRE1;
        int n = o / CDIM, k = o % CDIM;
        Wt[160 * CDIM + o] = tf32r(dec_w1[k * 64 + n]);
    } else if (idx < PRE3) {
        int o = idx - PRE2;
        int n = o / 64, k = o % 64;
        Wt[160 * CDIM + 64 * CDIM + o] = tf32r(dec_w2[k * CDIM + n]);
    } else {
        int o = idx - PRE3;
        int f = o / (CDIM * 32);
        int rem = o % (CDIM * 32);
        int c = rem >> 5, j = rem & 31;
        Wm[o] = tf32r(maa_w2[(f * 32 + j) * CDIM + c]);
    }
}

// ---------------- K1: q_shift + maa_x mix (float4) ----------------
#define C4 (CDIM/4)
__global__ void shift_mix_kernel(const float* __restrict__ x,
                                 const float* __restrict__ maa_x,
                                 float* __restrict__ xx, float* __restrict__ xxx,
                                 int total4)
{
    int idx = blockIdx.x * blockDim.x + threadIdx.x;
    if (idx >= total4) return;
    int c4 = idx % C4;
    int t = (idx / C4) % TDIM;
    int b = idx / (C4 * TDIM);
    int d4 = c4 & 15;
    int hh = t >> 5, ww = t & 31;
    int st = -1;
    if (d4 < 4)       { if (ww >= 1)      st = t - 1;  }
    else if (d4 < 8)  { if (ww < PW - 1)  st = t + 1;  }
    else if (d4 < 12) { if (hh >= 1)      st = t - PW; }
    else              { if (hh < PH - 1)  st = t + PW; }
    float4 sh = make_float4(0.f, 0.f, 0.f, 0.f);
    if (st >= 0)
        sh = *(const float4*)(x + (((size_t)b * TDIM + st) * C4 + c4) * 4);
    float4 xv = *(const float4*)(x + (size_t)idx * 4);
    float4 mm = *(const float4*)(maa_x + c4 * 4);
    float4 dd, ox;
    dd.x = sh.x - xv.x; dd.y = sh.y - xv.y; dd.z = sh.z - xv.z; dd.w = sh.w - xv.w;
    ox.x = tf32r(xv.x + dd.x * mm.x);
    ox.y = tf32r(xv.y + dd.y * mm.y);
    ox.z = tf32r(xv.z + dd.z * mm.z);
    ox.w = tf32r(xv.w + dd.w * mm.w);
    *(float4*)(xx + (size_t)idx * 4) = dd;
    *(float4*)(xxx + (size_t)idx * 4) = ox;
}

// ---------------- mma.sync tf32 GEMM (2-stage, proven) ----------------
#define ASTR   36
#define ASZ    (128*ASTR)
#define GT_SMEM (4*ASZ*4)   // 73728 B

template<int EPI>
__device__ __forceinline__ float epi_f(float a, const float* bias, int n) {
    if (EPI == 1) return tanhf(a);
    if (EPI == 2) return fmaxf(a, 0.f);
    if (EPI == 3) return a + bias[n];
    if (EPI == 4) return tf32r(tanhf(a));
    return a;
}

__device__ __forceinline__ void gt_issue(float* sm, const float* __restrict__ A,
                                         const float* __restrict__ Bm,
                                         int m0, int n0, int it, int tid, int N, int K)
{
    int s = it & 1;
    float* As = sm + s * ASZ;
    float* Bs = sm + 2 * ASZ + s * ASZ;
    int k0 = it * 32;
#pragma unroll
    for (int p = 0; p < 4; p++) {
        int c = tid + p * 256;
        int row = c >> 3, kc = (c & 7) << 2;
        cp16(As + row * ASTR + kc, A + (size_t)(m0 + row) * K + k0 + kc);
    }
#pragma unroll
    for (int p = 0; p < 4; p++) {
        int c = tid + p * 256;
        int row = c >> 3, kc = (c & 7) << 2;
        int valid = (n0 + row) < N;
        const float* src = Bm + (valid ? ((size_t)(n0 + row) * K + k0 + kc) : 0);
        cp16z(Bs + row * ASTR + kc, src, valid ? 16 : 0);
    }
    asm volatile("cp.async.commit_group;" ::: "memory");
}

__device__ __forceinline__ void gt_mma_stage(const float* As, const float* Bs,
                                             int warp_m, int warp_n, int lane,
                                             float acc[4][4][4])
{
    int lrow = lane & 7;
    int a_m = ((lane >> 3) & 1) * 8 + lrow;
    int a_k = (lane >> 4) * 4;
    int b_row8 = ((lane >> 4) & 1) * 8 + lrow;
    int b_k = ((lane >> 3) & 1) * 4;
#pragma unroll
    for (int ks = 0; ks < 4; ks++) {
        unsigned af[4][4], bf[4][2];
#pragma unroll
        for (int mi = 0; mi < 4; mi++) {
            const float* p = As + (warp_m * 64 + mi * 16 + a_m) * ASTR + ks * 8 + a_k;
            unsigned ad = (unsigned)__cvta_generic_to_shared(p);
            asm volatile("ldmatrix.sync.aligned.m8n8.x4.shared.b16 {%0,%1,%2,%3}, [%4];"
                : "=r"(af[mi][0]), "=r"(af[mi][1]), "=r"(af[mi][2]), "=r"(af[mi][3]) : "r"(ad));
        }
#pragma unroll
        for (int np = 0; np < 2; np++) {
            const float* p = Bs + (warp_n * 32 + np * 16 + b_row8) * ASTR + ks * 8 + b_k;
            unsigned ad = (unsigned)__cvta_generic_to_shared(p);
            asm volatile("ldmatrix.sync.aligned.m8n8.x4.shared.b16 {%0,%1,%2,%3}, [%4];"
                : "=r"(bf[np * 2][0]), "=r"(bf[np * 2][1]),
                  "=r"(bf[np * 2 + 1][0]), "=r"(bf[np * 2 + 1][1]) : "r"(ad));
        }
#pragma unroll
        for (int mi = 0; mi < 4; mi++)
#pragma unroll
            for (int ni = 0; ni < 4; ni++) {
                asm volatile(
                    "mma.sync.aligned.m16n8k8.row.col.f32.tf32.tf32.f32 "
                    "{%0,%1,%2,%3}, {%4,%5,%6,%7}, {%8,%9}, {%0,%1,%2,%3};"
                    : "+f"(acc[mi][ni][0]), "+f"(acc[mi][ni][1]),
                      "+f"(acc[mi][ni][2]), "+f"(acc[mi][ni][3])
                    : "r"(af[mi][0]), "r"(af[mi][1]), "r"(af[mi][2]), "r"(af[mi][3]),
                      "r"(bf[ni][0]), "r"(bf[ni][1]));
            }
    }
}

template<int EPI, bool RELU_RT>
__device__ __forceinline__ void gt_body(const float* __restrict__ A, const float* __restrict__ Bm,
                                        float* __restrict__ Cm, int N, int K,
                                        const float* __restrict__ bias, int relu_flag)
{
    extern __shared__ __align__(16) float sm[];
    int tid = threadIdx.x;
    int lane = tid & 31, warp = tid >> 5;
    int warp_m = warp >> 2, warp_n = warp & 3;
    int m0 = blockIdx.y * 128, n0 = blockIdx.x * 128;

    float acc[4][4][4];
#pragma unroll
    for (int i = 0; i < 4; i++)
#pragma unroll
        for (int j = 0; j < 4; j++)
#pragma unroll
            for (int q = 0; q < 4; q++) acc[i][j][q] = 0.f;

    gt_issue(sm, A, Bm, m0, n0, 0, tid, N, K);

    const int NIT = K / 32;
#pragma unroll 1
    for (int it = 0; it < NIT; it++) {
        if (it + 1 < NIT) {
            gt_issue(sm, A, Bm, m0, n0, it + 1, tid, N, K);
            asm volatile("cp.async.wait_group 1;" ::: "memory");
        } else {
            asm volatile("cp.async.wait_group 0;" ::: "memory");
        }
        __syncthreads();
        int s = it & 1;
        gt_mma_stage(sm + s * ASZ, sm + 2 * ASZ + s * ASZ, warp_m, warp_n, lane, acc);
        __syncthreads();
    }

    int erow = lane >> 2, ecol = (lane & 3) * 2;
#pragma unroll
    for (int mi = 0; mi < 4; mi++) {
#pragma unroll
        for (int ni = 0; ni < 4; ni++) {
            int m = m0 + warp_m * 64 + mi * 16 + erow;
            int n = n0 + warp_n * 32 + ni * 8 + ecol;
            if (n < N) {
                float2 v0, v1;
                v0.x = epi_f<EPI>(acc[mi][ni][0], bias, n);
                v0.y = epi_f<EPI>(acc[mi][ni][1], bias, n + 1);
                v1.x = epi_f<EPI>(acc[mi][ni][2], bias, n);
                v1.y = epi_f<EPI>(acc[mi][ni][3], bias, n + 1);
                if (RELU_RT && relu_flag) {
                    v0.x = fmaxf(v0.x, 0.f); v0.y = fmaxf(v0.y, 0.f);
                    v1.x = fmaxf(v1.x, 0.f); v1.y = fmaxf(v1.y, 0.f);
                }
                *(float2*)(Cm + (size_t)m * N + n) = v0;
                *(float2*)(Cm + (size_t)(m + 8) * N + n) = v1;
            }
        }
    }
}

template<int EPI>
__global__ __launch_bounds__(256, 2) void gemm_tf32_kernel(
    const float* __restrict__ A, const float* __restrict__ Bm,
    float* __restrict__ Cm, int N, int K, const float* __restrict__ bias)
{
    gt_body<EPI, false>(A, Bm, Cm, N, K, bias, 0);
}

__global__ __launch_bounds__(256, 2) void gemm_tf32_batch5_kernel(
    const float* __restrict__ a0, const float* __restrict__ a1,
    const float* __restrict__ a2, const float* __restrict__ a3,
    const float* __restrict__ a4,
    const float* __restrict__ b0, const float* __restrict__ b1,
    const float* __restrict__ b2, const float* __restrict__ b3,
    const float* __restrict__ b4,
    float* __restrict__ c0, float* __restrict__ c1,
    float* __restrict__ c2, float* __restrict__ c3,
    float* __restrict__ c4,
    const float* __restrict__ bias4)
{
    int z = blockIdx.z;
    if (z < 4) {
        const float* A  = (z == 0) ? a0 : (z == 1) ? a1 : (z == 2) ? a2 : a3;
        const float* Bm = (z == 0) ? b0 : (z == 1) ? b1 : (z == 2) ? b2 : b3;
        float* Cm       = (z == 0) ? c0 : (z == 1) ? c1 : (z == 2) ? c2 : c3;
        gt_body<0, true>(A, Bm, Cm, CDIM, CDIM, nullptr, z == 3);
    } else {
        gt_body<3, false>(a4, b4, c4, CDIM, 64, bias4, 0);
    }
}

// ---------------- mix5 GEMM, 128x64 tile, smem-cached x/xx ----------------
#define M5_XS 0
#define M5_DS 9216
#define M5_AS 18432
#define M5_BS 23040
#define M5_SMEM (25344*4)

__global__ __launch_bounds__(256, 2) void mix5g_kernel(
    const float* __restrict__ tb, const float* __restrict__ Wm,
    const float* __restrict__ x, const float* __restrict__ xx,
    const float* __restrict__ mw, const float* __restrict__ mk,
    const float* __restrict__ mv, const float* __restrict__ mr,
    const float* __restrict__ mg,
    float* __restrict__ xw, float* __restrict__ xk, float* __restrict__ xv,
    float* __restrict__ xr, float* __restrict__ xg)
{
    extern __shared__ __align__(16) float sm[];
    int tid = threadIdx.x;
    int lane = tid & 31, warp = tid >> 5;
    int warp_m = warp >> 1, warp_n = warp & 1;
    int m0 = blockIdx.y * 128, n0 = blockIdx.x * 64;
    int erow = lane >> 2, ecol = (lane & 3) * 2;

#pragma unroll
    for (int p = 0; p < 8; p++) {
        int c = tid + p * 256;
        int row = c >> 4, c16 = c & 15;
        cp16(sm + M5_XS + row * 72 + c16 * 4, x  + (size_t)(m0 + row) * CDIM + n0 + c16 * 4);
        cp16(sm + M5_DS + row * 72 + c16 * 4, xx + (size_t)(m0 + row) * CDIM + n0 + c16 * 4);
    }
    asm volatile("cp.async.commit_group;" ::: "memory");

#pragma unroll 1
    for (int f = 0; f < 5; f++) {
#pragma unroll
        for (int p = 0; p < 4; p++) {
            int c = tid + p * 256;
            int row = c >> 3, kc = (c & 7) << 2;
            cp16(sm + M5_AS + row * ASTR + kc, tb + (size_t)(m0 + row) * 160 + f * 32 + kc);
        }
#pragma unroll
        for (int p = 0; p < 2; p++) {
            int c = tid + p * 256;
            int row = c >> 3, kc = (c & 7) << 2;
            cp16(sm + M5_BS + row * ASTR + kc, Wm + (size_t)f * CDIM * 32 + (size_t)(n0 + row) * 32 + kc);
        }
        asm volatile("cp.async.commit_group;" ::: "memory");
        asm volatile("cp.async.wait_group 0;" ::: "memory");
        __syncthreads();

        float acc[2][4][4];
#pragma unroll
        for (int i = 0; i < 2; i++)
#pragma unroll
            for (int j = 0; j < 4; j++)
#pragma unroll
                for (int q = 0; q < 4; q++) acc[i][j][q] = 0.f;

        {
            const float* As = sm + M5_AS;
            const float* Bs = sm + M5_BS;
            int lrow = lane & 7;
            int a_m = ((lane >> 3) & 1) * 8 + lrow;
            int a_k = (lane >> 4) * 4;
            int b_row8 = ((lane >> 4) & 1) * 8 + lrow;
            int b_k = ((lane >> 3) & 1) * 4;
#pragma unroll
            for (int ks = 0; ks < 4; ks++) {
                unsigned af[2][4], bf[4][2];
#pragma unroll
                for (int mi = 0; mi < 2; mi++) {
                    const float* p = As + (warp_m * 32 + mi * 16 + a_m) * ASTR + ks * 8 + a_k;
                    unsigned ad = (unsigned)__cvta_generic_to_shared(p);
                    asm volatile("ldmatrix.sync.aligned.m8n8.x4.shared.b16 {%0,%1,%2,%3}, [%4];"
                        : "=r"(af[mi][0]), "=r"(af[mi][1]), "=r"(af[mi][2]), "=r"(af[mi][3]) : "r"(ad));
                }
#pragma unroll
                for (int np = 0; np < 2; np++) {
                    const float* p = Bs + (warp_n * 32 + np * 16 + b_row8) * ASTR + ks * 8 + b_k;
                    unsigned ad = (unsigned)__cvta_generic_to_shared(p);
                    asm volatile("ldmatrix.sync.aligned.m8n8.x4.shared.b16 {%0,%1,%2,%3}, [%4];"
                        : "=r"(bf[np * 2][0]), "=r"(bf[np * 2][1]),
                          "=r"(bf[np * 2 + 1][0]), "=r"(bf[np * 2 + 1][1]) : "r"(ad));
                }
#pragma unroll
                for (int mi = 0; mi < 2; mi++)
#pragma unroll
                    for (int ni = 0; ni < 4; ni++) {
                        asm volatile(
                            "mma.sync.aligned.m16n8k8.row.col.f32.tf32.tf32.f32 "
                            "{%0,%1,%2,%3}, {%4,%5,%6,%7}, {%8,%9}, {%0,%1,%2,%3};"
                            : "+f"(acc[mi][ni][0]), "+f"(acc[mi][ni][1]),
                              "+f"(acc[mi][ni][2]), "+f"(acc[mi][ni][3])
                            : "r"(af[mi][0]), "r"(af[mi][1]), "r"(af[mi][2]), "r"(af[mi][3]),
                              "r"(bf[ni][0]), "r"(bf[ni][1]));
                    }
            }
        }

        const float* maa_f = (f == 0) ? mw : (f == 1) ? mk : (f == 2) ? mv : (f == 3) ? mr : mg;
        float* out_f       = (f == 0) ? xw : (f == 1) ? xk : (f == 2) ? xv : (f == 3) ? xr : xg;
#pragma unroll
        for (int mi = 0; mi < 2; mi++) {
#pragma unroll
            for (int ni = 0; ni < 4; ni++) {
                int ml = warp_m * 32 + mi * 16 + erow;
                int nl = warp_n * 32 + ni * 8 + ecol;
                int ng = n0 + nl;
                float2 xa = *(const float2*)(sm + M5_XS + ml * 72 + nl);
                float2 xb = *(const float2*)(sm + M5_XS + (ml + 8) * 72 + nl);
                float2 da = *(const float2*)(sm + M5_DS + ml * 72 + nl);
                float2 db = *(const float2*)(sm + M5_DS + (ml + 8) * 72 + nl);
                float2 ma = *(const float2*)(maa_f + ng);
                float2 v0, v1;
                v0.x = tf32r(xa.x + da.x * (ma.x + acc[mi][ni][0]));
                v0.y = tf32r(xa.y + da.y * (ma.y + acc[mi][ni][1]));
                v1.x = tf32r(xb.x + db.x * (ma.x + acc[mi][ni][2]));
                v1.y = tf32r(xb.y + db.y * (ma.y + acc[mi][ni][3]));
                *(float2*)(out_f + (size_t)(m0 + ml) * CDIM + ng) = v0;
                *(float2*)(out_f + (size_t)(m0 + ml + 8) * CDIM + ng) = v1;
            }
        }
        __syncthreads();
    }
}

// ---------------- K4: WKV6 recurrence (no fusion) ----------------
__device__ __forceinline__ void wkv_issue(int ci, float* rsb, float* ksb,
        float* vsb, float* wsb,
        const float* rp, const float* kp, const float* vp, const float* wpp,
        size_t base, int tid)
{
#pragma unroll
    for (int p = 0; p < 2; p++) {
        int idx = tid + p * 256;
        int arr = idx >> 7;
        int rem = idx & 127;
        int tc = rem >> 4, c4 = (rem & 15) << 2;
        size_t gofs = base + (size_t)(ci * 8 + tc) * CDIM + c4;
        float* dst; const float* src;
        if (arr == 0)      { dst = rsb + tc * 64 + c4; src = rp  + gofs; }
        else if (arr == 1) { dst = ksb + tc * 64 + c4; src = kp  + gofs; }
        else if (arr == 2) { dst = vsb + tc * 64 + c4; src = vp  + gofs; }
        else               { dst = wsb + tc * 64 + c4; src = wpp + gofs; }
        cp16(dst, src);
    }
    asm volatile("cp.async.commit_group;" ::: "memory");
}

__global__ __launch_bounds__(256, 1) void wkv6_kernel(
    const float* __restrict__ rp, const float* __restrict__ kp,
    const float* __restrict__ vp, const float* __restrict__ wp_,
    const float* __restrict__ up, float* __restrict__ yp)
{
    __shared__ __align__(16) float rs[2][512], ks[2][512], vs[2][512], ws[2][512];
    __shared__ float us[64], ruks[8];
    int tid = threadIdx.x;
    int b = blockIdx.x / NHEAD, h = blockIdx.x % NHEAD;
    size_t base = (size_t)b * TDIM * CDIM + h * HS;
    if (tid < 64) us[tid] = up[h * HS + tid];
    int i = tid >> 2, jq = tid & 3;
    int lane = tid & 31, warp = tid >> 5;

    float S[16];
#pragma unroll
    for (int q = 0; q < 16; q++) S[q] = 0.f;

    wkv_issue(0, rs[0], ks[0], vs[0], ws[0], rp, kp, vp, wp_, base, tid);

#pragma unroll 1
    for (int ci = 0; ci < TDIM / 8; ci++) {
        int buf = ci & 1;
        asm volatile("cp.async.wait_group 0;" ::: "memory");
        __syncthreads();
        for (int idx = tid; idx < 512; idx += 256)
            ws[buf][idx] = expf(-expf(ws[buf][idx]));
        {
            float p = rs[buf][warp * 64 + lane] * us[lane] * ks[buf][warp * 64 + lane]
                    + rs[buf][warp * 64 + 32 + lane] * us[32 + lane] * ks[buf][warp * 64 + 32 + lane];
#pragma unroll
            for (int o = 16; o; o >>= 1) p += __shfl_xor_sync(0xffffffffu, p, o);
            if (lane == 0) ruks[warp] = p;
        }
        __syncthreads();
        if (ci + 1 < TDIM / 8) {
            int nb = buf ^ 1;
            wkv_issue(ci + 1, rs[nb], ks[nb], vs[nb], ws[nb], rp, kp, vp, wp_, base, tid);
        }
#pragma unroll 1
        for (int tc = 0; tc < 8; tc++) {
            float vi = vs[buf][tc * 64 + i];
            const float4* r4 = (const float4*)&rs[buf][tc * 64 + jq * 16];
            const float4* k4 = (const float4*)&ks[buf][tc * 64 + jq * 16];
            const float4* w4 = (const float4*)&ws[buf][tc * 64 + jq * 16];
            float yps = 0.f;
#pragma unroll
            for (int q = 0; q < 4; q++) {
                float4 rv = r4[q], kv = k4[q], wv = w4[q];
                yps += rv.x * S[q * 4 + 0]; S[q * 4 + 0] = wv.x * S[q * 4 + 0] + kv.x * vi;
                yps += rv.y * S[q * 4 + 1]; S[q * 4 + 1] = wv.y * S[q * 4 + 1] + kv.y * vi;
                yps += rv.z * S[q * 4 + 2]; S[q * 4 + 2] = wv.z * S[q * 4 + 2] + kv.z * vi;
                yps += rv.w * S[q * 4 + 3]; S[q * 4 + 3] = wv.w * S[q * 4 + 3] + kv.w * vi;
            }
            yps += __shfl_xor_sync(0xffffffffu, yps, 1);
            yps += __shfl_xor_sync(0xffffffffu, yps, 2);
            if (jq == 0)
                yp[base + (size_t)(ci * 8 + tc) * CDIM + i] = yps + vi * ruks[tc];
        }
    }
}

// ---------------- K5: per-head GroupNorm * g ----------------
__global__ void gn_mul_kernel(const float* __restrict__ y,
                              const float* __restrict__ lw, const float* __restrict__ lb,
                              const float* __restrict__ g, float* __restrict__ out)
{
    int row = blockIdx.x;
    int warp = threadIdx.x >> 5, lane = threadIdx.x & 31;
    size_t o = (size_t)row * CDIM + warp * HS;
    float v0 = y[o + lane], v1 = y[o + 32 + lane];
    float s = v0 + v1, ss = v0 * v0 + v1 * v1;
#pragma unroll
    for (int off = 16; off; off >>= 1) {
        s  += __shfl_xor_sync(0xffffffffu, s,  off);
        ss += __shfl_xor_sync(0xffffffffu, ss, off);
    }
    float mean = s * (1.f / HS);
    float var  = ss * (1.f / HS) - mean * mean;
    float inv  = rsqrtf(var + 1e-5f);
    int c0 = warp * HS + lane, c1 = c0 + 32;
    float n0 = (v0 - mean) * inv * lw[c0] + lb[c0];
    float n1 = (v1 - mean) * inv * lw[c1] + lb[c1];
    out[o + lane]      = tf32r(n0 * g[o + lane]);
    out[o + 32 + lane] = tf32r(n1 * g[o + 32 + lane]);
}

// ---------------- launcher ----------------
extern "C" void kernel_launch(void* const* d_in, const int* in_sizes, int n_in,
                              void* d_out, int out_size)
{
    const float* x          = (const float*)d_in[0];
    const float* W_r        = (const float*)d_in[1];
    const float* W_k        = (const float*)d_in[2];
    const float* W_v        = (const float*)d_in[3];
    const float* W_g        = (const float*)d_in[4];
    const float* W_o        = (const float*)d_in[5];
    const float* maa_x      = (const float*)d_in[6];
    const float* maa_w      = (const float*)d_in[7];
    const float* maa_k      = (const float*)d_in[8];
    const float* maa_v      = (const float*)d_in[9];
    const float* maa_r      = (const float*)d_in[10];
    const float* maa_g      = (const float*)d_in[11];
    const float* maa_w1     = (const float*)d_in[12];
    const float* maa_w2     = (const float*)d_in[13];
    const float* time_decay = (const float*)d_in[14];
    const float* dec_w1     = (const float*)d_in[15];
    const float* dec_w2     = (const float*)d_in[16];
    const float* faaaa      = (const float*)d_in[17];
    const float* ln_w       = (const float*)d_in[18];
    const float* ln_b       = (const float*)d_in[19];
    float* out = (float*)d_out;

    float *xx, *xxx, *tb, *xw, *xk, *xv, *xr, *xg, *rb, *kb, *vb, *gb, *h1, *wb, *yb, *yg, *Wc, *Wt, *Wm;
    cudaGetSymbolAddress((void**)&xx,  g_xx);
    cudaGetSymbolAddress((void**)&xxx, g_xxx);
    cudaGetSymbolAddress((void**)&tb,  g_t);
    cudaGetSymbolAddress((void**)&xw,  g_xw);
    cudaGetSymbolAddress((void**)&xk,  g_xk);
    cudaGetSymbolAddress((void**)&xv,  g_xv);
    cudaGetSymbolAddress((void**)&xr,  g_xr);
    cudaGetSymbolAddress((void**)&xg,  g_xg);
    cudaGetSymbolAddress((void**)&rb,  g_r);
    cudaGetSymbolAddress((void**)&kb,  g_k);
    cudaGetSymbolAddress((void**)&vb,  g_v);
    cudaGetSymbolAddress((void**)&gb,  g_g);
    cudaGetSymbolAddress((void**)&h1,  g_h1);
    cudaGetSymbolAddress((void**)&wb,  g_w);
    cudaGetSymbolAddress((void**)&yb,  g_y);
    cudaGetSymbolAddress((void**)&yg,  g_yg);
    cudaGetSymbolAddress((void**)&Wc,  g_Wc);
    cudaGetSymbolAddress((void**)&Wt,  g_Wt);
    cudaGetSymbolAddress((void**)&Wm,  g_Wm);

    const int NW = CDIM * CDIM;
    float* Wr_c = Wc + 0 * NW;
    float* Wk_c = Wc + 1 * NW;
    float* Wv_c = Wc + 2 * NW;
    float* Wg_c = Wc + 3 * NW;
    float* Wo_c = Wc + 4 * NW;
    float* W1t  = Wt;
    float* D1t  = Wt + 160 * CDIM;
    float* D2t  = Wt + 160 * CDIM + 64 * CDIM;

    cudaFuncSetAttribute(gemm_tf32_kernel<0>, cudaFuncAttributeMaxDynamicSharedMemorySize, GT_SMEM);
    cudaFuncSetAttribute(gemm_tf32_kernel<4>, cudaFuncAttributeMaxDynamicSharedMemorySize, GT_SMEM);
    cudaFuncSetAttribute(gemm_tf32_batch5_kernel, cudaFuncAttributeMaxDynamicSharedMemorySize, GT_SMEM);
    cudaFuncSetAttribute(mix5g_kernel, cudaFuncAttributeMaxDynamicSharedMemorySize, M5_SMEM);

    int total4 = NR * C4;

    prep_all_kernel<<<(PRE4 + 255) / 256, 256>>>(W_r, W_k, W_v, W_g, W_o,            // 1
        maa_w1, dec_w1, dec_w2, maa_w2, Wc, Wt, Wm);
    shift_mix_kernel<<<(total4 + 255) / 256, 256>>>(x, maa_x, xx, xxx, total4);      // 2
    {                                                                                 // 3
        dim3 grid(2, NR / 128);
        gemm_tf32_kernel<4><<<grid, 256, GT_SMEM>>>(xxx, W1t, tb, 160, CDIM, nullptr);
    }
    {                                                                                 // 4
        dim3 grid(CDIM / 64, NR / 128);
        mix5g_kernel<<<grid, 256, M5_SMEM>>>(tb, Wm, x, xx,
            maa_w, maa_k, maa_v, maa_r, maa_g, xw, xk, xv, xr, xg);
    }
    {                                                                                 // 5
        dim3 grid(1, NR / 128);
        gemm_tf32_kernel<4><<<grid, 256, GT_SMEM>>>(xw, D1t, h1, 64, CDIM, nullptr);
    }
    {                                                                                 // 6
        dim3 grid(6, NR / 128, 5);
        gemm_tf32_batch5_kernel<<<grid, 256, GT_SMEM>>>(
            xr, xk, xv, xg, h1, Wr_c, Wk_c, Wv_c, Wg_c, D2t,
            rb, kb, vb, gb, wb, time_decay);
    }
    wkv6_kernel<<<8 * NHEAD, 256>>>(rb, kb, vb, wb, faaaa, yb);                       // 7
    gn_mul_kernel<<<NR, 384>>>(yb, ln_w, ln_b, gb, yg);                               // 8
    {                                                                                 // 9
        dim3 gcc(6, NR / 128);
        gemm_tf32_kernel<0><<<gcc, 256, GT_SMEM>>>(yg, Wo_c, out, CDIM, CDIM, nullptr);
    }
}

// round 14
// speedup vs baseline: 1.0743x; 1.0365x over previous
#include <cuda_runtime.h>
#include <math.h>

#define TDIM 1024
#define CDIM 768
#define PH 32
#define PW 32
#define NHEAD 12
#define HS 64
#define NR (8*1024)

__device__ float g_xx [NR*CDIM];
__device__ float g_xxx[NR*CDIM];
__device__ float g_t  [NR*160];
__device__ float g_xw [NR*CDIM];
__device__ float g_xk [NR*CDIM];
__device__ float g_xv [NR*CDIM];
__device__ float g_xr [NR*CDIM];
__device__ float g_xg [NR*CDIM];
__device__ float g_r  [NR*CDIM];
__device__ float g_k  [NR*CDIM];
__device__ float g_v  [NR*CDIM];
__device__ float g_g  [NR*CDIM];
__device__ float g_h1 [NR*64];
__device__ float g_w  [NR*CDIM];
__device__ float g_y  [NR*CDIM];
__device__ float g_yg [NR*CDIM];
__device__ float g_ruk[NR*NHEAD];
__device__ float g_Wc [5*CDIM*CDIM];
__device__ float g_Wt [160*CDIM + 64*CDIM + CDIM*64];
__device__ float g_Wm [5*CDIM*32];

__device__ __forceinline__ float tf32r(float x) {
    unsigned u;
    asm("cvt.rna.tf32.f32 %0, %1;" : "=r"(u) : "f"(x));
    return __uint_as_float(u);
}
__device__ __forceinline__ void cp16(void* dst, const void* src) {
    unsigned d = (unsigned)__cvta_generic_to_shared(dst);
    asm volatile("cp.async.cg.shared.global [%0], [%1], 16;" :: "r"(d), "l"(src) : "memory");
}
__device__ __forceinline__ void cp16z(void* dst, const void* src, int sz) {
    unsigned d = (unsigned)__cvta_generic_to_shared(dst);
    asm volatile("cp.async.cg.shared.global [%0], [%1], 16, %2;" :: "r"(d), "l"(src), "r"(sz) : "memory");
}

// ---------------- fused weight prep + q_shift mix (one launch) ----------------
#define NW_ (CDIM*CDIM)
#define PRE0 (5*NW_)
#define PRE1 (PRE0 + 160*CDIM)
#define PRE2 (PRE1 + 64*CDIM)
#define PRE3 (PRE2 + CDIM*64)
#define PRE4 (PRE3 + 5*CDIM*32)
#define C4 (CDIM/4)
#define PRE5 (PRE4 + NR*C4)
__global__ void prep_shift_kernel(const float* __restrict__ w0, const float* __restrict__ w1,
                                  const float* __restrict__ w2, const float* __restrict__ w3,
                                  const float* __restrict__ w4,
                                  const float* __restrict__ maa_w1, const float* __restrict__ dec_w1,
                                  const float* __restrict__ dec_w2, const float* __restrict__ maa_w2,
                                  float* __restrict__ Wc, float* __restrict__ Wt, float* __restrict__ Wm,
                                  const float* __restrict__ x, const float* __restrict__ maa_x,
                                  float* __restrict__ xx, float* __restrict__ xxx)
{
    int idx = blockIdx.x * blockDim.x + threadIdx.x;
    if (idx >= PRE5) return;
    if (idx < PRE0) {
        int m = idx / NW_, r = idx % NW_;
        const float* src = (m == 0) ? w0 : (m == 1) ? w1 : (m == 2) ? w2 : (m == 3) ? w3 : w4;
        Wc[idx] = tf32r(src[r]);
    } else if (idx < PRE1) {
        int o = idx - PRE0;
        int n = o / CDIM, k = o % CDIM;
        Wt[o] = tf32r(maa_w1[k * 160 + n]);
    } else if (idx < PRE2) {
        int o = idx - PRE1;
        int n = o / CDIM, k = o % CDIM;
        Wt[160 * CDIM + o] = tf32r(dec_w1[k * 64 + n]);
    } else if (idx < PRE3) {
        int o = idx - PRE2;
        int n = o / 64, k = o % 64;
        Wt[160 * CDIM + 64 * CDIM + o] = tf32r(dec_w2[k * CDIM + n]);
    } else if (idx < PRE4) {
        int o = idx - PRE3;
        int f = o / (CDIM * 32);
        int rem = o % (CDIM * 32);
        int c = rem >> 5, j = rem & 31;
        Wm[o] = tf32r(maa_w2[(f * 32 + j) * CDIM + c]);
    } else {
        int e = idx - PRE4;            // float4 element index
        int c4 = e % C4;
        int t = (e / C4) % TDIM;
        int b = e / (C4 * TDIM);
        int d4 = c4 & 15;
        int hh = t >> 5, ww = t & 31;
        int st = -1;
        if (d4 < 4)       { if (ww >= 1)      st = t - 1;  }
        else if (d4 < 8)  { if (ww < PW - 1)  st = t + 1;  }
        else if (d4 < 12) { if (hh >= 1)      st = t - PW; }
        else              { if (hh < PH - 1)  st = t + PW; }
        float4 sh = make_float4(0.f, 0.f, 0.f, 0.f);
        if (st >= 0)
            sh = *(const float4*)(x + (((size_t)b * TDIM + st) * C4 + c4) * 4);
        float4 xv = *(const float4*)(x + (size_t)e * 4);
        float4 mm = *(const float4*)(maa_x + c4 * 4);
        float4 dd, ox;
        dd.x = sh.x - xv.x; dd.y = sh.y - xv.y; dd.z = sh.z - xv.z; dd.w = sh.w - xv.w;
        ox.x = tf32r(xv.x + dd.x * mm.x);
        ox.y = tf32r(xv.y + dd.y * mm.y);
        ox.z = tf32r(xv.z + dd.z * mm.z);
        ox.w = tf32r(xv.w + dd.w * mm.w);
        *(float4*)(xx + (size_t)e * 4) = dd;
        *(float4*)(xxx + (size_t)e * 4) = ox;
    }
}

// ---------------- mma.sync tf32 GEMM (2-stage, proven) ----------------
#define ASTR   36
#define ASZ    (128*ASTR)
#define GT_SMEM (4*ASZ*4)   // 73728 B

template<int EPI>
__device__ __forceinline__ float epi_f(float a, const float* bias, int n) {
    if (EPI == 1) return tanhf(a);
    if (EPI == 2) return fmaxf(a, 0.f);
    if (EPI == 3) return a + bias[n];
    if (EPI == 4) return tf32r(tanhf(a));
    if (EPI == 5) return expf(-expf(a + bias[n]));   // decay factor for wkv
    return a;
}

__device__ __forceinline__ void gt_issue(float* sm, const float* __restrict__ A,
                                         const float* __restrict__ Bm,
                                         int m0, int n0, int it, int tid, int N, int K)
{
    int s = it & 1;
    float* As = sm + s * ASZ;
    float* Bs = sm + 2 * ASZ + s * ASZ;
    int k0 = it * 32;
#pragma unroll
    for (int p = 0; p < 4; p++) {
        int c = tid + p * 256;
        int row = c >> 3, kc = (c & 7) << 2;
        cp16(As + row * ASTR + kc, A + (size_t)(m0 + row) * K + k0 + kc);
    }
#pragma unroll
    for (int p = 0; p < 4; p++) {
        int c = tid + p * 256;
        int row = c >> 3, kc = (c & 7) << 2;
        int valid = (n0 + row) < N;
        const float* src = Bm + (valid ? ((size_t)(n0 + row) * K + k0 + kc) : 0);
        cp16z(Bs + row * ASTR + kc, src, valid ? 16 : 0);
    }
    asm volatile("cp.async.commit_group;" ::: "memory");
}

__device__ __forceinline__ void gt_mma_stage(const float* As, const float* Bs,
                                             int warp_m, int warp_n, int lane,
                                             float acc[4][4][4])
{
    int lrow = lane & 7;
    int a_m = ((lane >> 3) & 1) * 8 + lrow;
    int a_k = (lane >> 4) * 4;
    int b_row8 = ((lane >> 4) & 1) * 8 + lrow;
    int b_k = ((lane >> 3) & 1) * 4;
#pragma unroll
    for (int ks = 0; ks < 4; ks++) {
        unsigned af[4][4], bf[4][2];
#pragma unroll
        for (int mi = 0; mi < 4; mi++) {
            const float* p = As + (warp_m * 64 + mi * 16 + a_m) * ASTR + ks * 8 + a_k;
            unsigned ad = (unsigned)__cvta_generic_to_shared(p);
            asm volatile("ldmatrix.sync.aligned.m8n8.x4.shared.b16 {%0,%1,%2,%3}, [%4];"
                : "=r"(af[mi][0]), "=r"(af[mi][1]), "=r"(af[mi][2]), "=r"(af[mi][3]) : "r"(ad));
        }
#pragma unroll
        for (int np = 0; np < 2; np++) {
            const float* p = Bs + (warp_n * 32 + np * 16 + b_row8) * ASTR + ks * 8 + b_k;
            unsigned ad = (unsigned)__cvta_generic_to_shared(p);
            asm volatile("ldmatrix.sync.aligned.m8n8.x4.shared.b16 {%0,%1,%2,%3}, [%4];"
                : "=r"(bf[np * 2][0]), "=r"(bf[np * 2][1]),
                  "=r"(bf[np * 2 + 1][0]), "=r"(bf[np * 2 + 1][1]) : "r"(ad));
        }
#pragma unroll
        for (int mi = 0; mi < 4; mi++)
#pragma unroll
            for (int ni = 0; ni < 4; ni++) {
                asm volatile(
                    "mma.sync.aligned.m16n8k8.row.col.f32.tf32.tf32.f32 "
                    "{%0,%1,%2,%3}, {%4,%5,%6,%7}, {%8,%9}, {%0,%1,%2,%3};"
                    : "+f"(acc[mi][ni][0]), "+f"(acc[mi][ni][1]),
                      "+f"(acc[mi][ni][2]), "+f"(acc[mi][ni][3])
                    : "r"(af[mi][0]), "r"(af[mi][1]), "r"(af[mi][2]), "r"(af[mi][3]),
                      "r"(bf[ni][0]), "r"(bf[ni][1]));
            }
    }
}

template<int EPI, bool RELU_RT>
__device__ __forceinline__ void gt_body(const float* __restrict__ A, const float* __restrict__ Bm,
                                        float* __restrict__ Cm, int N, int K,
                                        const float* __restrict__ bias, int relu_flag)
{
    extern __shared__ __align__(16) float sm[];
    int tid = threadIdx.x;
    int lane = tid & 31, warp = tid >> 5;
    int warp_m = warp >> 2, warp_n = warp & 3;
    int m0 = blockIdx.y * 128, n0 = blockIdx.x * 128;

    float acc[4][4][4];
#pragma unroll
    for (int i = 0; i < 4; i++)
#pragma unroll
        for (int j = 0; j < 4; j++)
#pragma unroll
            for (int q = 0; q < 4; q++) acc[i][j][q] = 0.f;

    gt_issue(sm, A, Bm, m0, n0, 0, tid, N, K);

    const int NIT = K / 32;
#pragma unroll 1
    for (int it = 0; it < NIT; it++) {
        if (it + 1 < NIT) {
            gt_issue(sm, A, Bm, m0, n0, it + 1, tid, N, K);
            asm volatile("cp.async.wait_group 1;" ::: "memory");
        } else {
            asm volatile("cp.async.wait_group 0;" ::: "memory");
        }
        __syncthreads();
        int s = it & 1;
        gt_mma_stage(sm + s * ASZ, sm + 2 * ASZ + s * ASZ, warp_m, warp_n, lane, acc);
        __syncthreads();
    }

    int erow = lane >> 2, ecol = (lane & 3) * 2;
#pragma unroll
    for (int mi = 0; mi < 4; mi++) {
#pragma unroll
        for (int ni = 0; ni < 4; ni++) {
            int m = m0 + warp_m * 64 + mi * 16 + erow;
            int n = n0 + warp_n * 32 + ni * 8 + ecol;
            if (n < N) {
                float2 v0, v1;
                v0.x = epi_f<EPI>(acc[mi][ni][0], bias, n);
                v0.y = epi_f<EPI>(acc[mi][ni][1], bias, n + 1);
                v1.x = epi_f<EPI>(acc[mi][ni][2], bias, n);
                v1.y = epi_f<EPI>(acc[mi][ni][3], bias, n + 1);
                if (RELU_RT && relu_flag) {
                    v0.x = fmaxf(v0.x, 0.f); v0.y = fmaxf(v0.y, 0.f);
                    v1.x = fmaxf(v1.x, 0.f); v1.y = fmaxf(v1.y, 0.f);
                }
                *(float2*)(Cm + (size_t)m * N + n) = v0;
                *(float2*)(Cm + (size_t)(m + 8) * N + n) = v1;
            }
        }
    }
}

template<int EPI>
__global__ __launch_bounds__(256, 2) void gemm_tf32_kernel(
    const float* __restrict__ A, const float* __restrict__ Bm,
    float* __restrict__ Cm, int N, int K, const float* __restrict__ bias)
{
    gt_body<EPI, false>(A, Bm, Cm, N, K, bias, 0);
}

__global__ __launch_bounds__(256, 2) void gemm_tf32_batch5_kernel(
    const float* __restrict__ a0, const float* __restrict__ a1,
    const float* __restrict__ a2, const float* __restrict__ a3,
    const float* __restrict__ a4,
    const float* __restrict__ b0, const float* __restrict__ b1,
    const float* __restrict__ b2, const float* __restrict__ b3,
    const float* __restrict__ b4,
    float* __restrict__ c0, float* __restrict__ c1,
    float* __restrict__ c2, float* __restrict__ c3,
    float* __restrict__ c4,
    const float* __restrict__ bias4)
{
    int z = blockIdx.z;
    if (z < 4) {
        const float* A  = (z == 0) ? a0 : (z == 1) ? a1 : (z == 2) ? a2 : a3;
        const float* Bm = (z == 0) ? b0 : (z == 1) ? b1 : (z == 2) ? b2 : b3;
        float* Cm       = (z == 0) ? c0 : (z == 1) ? c1 : (z == 2) ? c2 : c3;
        gt_body<0, true>(A, Bm, Cm, CDIM, CDIM, nullptr, z == 3);
    } else {
        gt_body<5, false>(a4, b4, c4, CDIM, 64, bias4, 0);   // w stored as exp(-exp(w))
    }
}

// ---------------- mix5 GEMM, 128x64 tile, smem-cached x/xx ----------------
#define M5_XS 0
#define M5_DS 9216
#define M5_AS 18432
#define M5_BS 23040
#define M5_SMEM (25344*4)

__global__ __launch_bounds__(256, 2) void mix5g_kernel(
    const float* __restrict__ tb, const float* __restrict__ Wm,
    const float* __restrict__ x, const float* __restrict__ xx,
    const float* __restrict__ mw, const float* __restrict__ mk,
    const float* __restrict__ mv, const float* __restrict__ mr,
    const float* __restrict__ mg,
    float* __restrict__ xw, float* __restrict__ xk, float* __restrict__ xv,
    float* __restrict__ xr, float* __restrict__ xg)
{
    extern __shared__ __align__(16) float sm[];
    int tid = threadIdx.x;
    int lane = tid & 31, warp = tid >> 5;
    int warp_m = warp >> 1, warp_n = warp & 1;
    int m0 = blockIdx.y * 128, n0 = blockIdx.x * 64;
    int erow = lane >> 2, ecol = (lane & 3) * 2;

#pragma unroll
    for (int p = 0; p < 8; p++) {
        int c = tid + p * 256;
        int row = c >> 4, c16 = c & 15;
        cp16(sm + M5_XS + row * 72 + c16 * 4, x  + (size_t)(m0 + row) * CDIM + n0 + c16 * 4);
        cp16(sm + M5_DS + row * 72 + c16 * 4, xx + (size_t)(m0 + row) * CDIM + n0 + c16 * 4);
    }
    asm volatile("cp.async.commit_group;" ::: "memory");

#pragma unroll 1
    for (int f = 0; f < 5; f++) {
#pragma unroll
        for (int p = 0; p < 4; p++) {
            int c = tid + p * 256;
            int row = c >> 3, kc = (c & 7) << 2;
            cp16(sm + M5_AS + row * ASTR + kc, tb + (size_t)(m0 + row) * 160 + f * 32 + kc);
        }
#pragma unroll
        for (int p = 0; p < 2; p++) {
            int c = tid + p * 256;
            int row = c >> 3, kc = (c & 7) << 2;
            cp16(sm + M5_BS + row * ASTR + kc, Wm + (size_t)f * CDIM * 32 + (size_t)(n0 + row) * 32 + kc);
        }
        asm volatile("cp.async.commit_group;" ::: "memory");
        asm volatile("cp.async.wait_group 0;" ::: "memory");
        __syncthreads();

        float acc[2][4][4];
#pragma unroll
        for (int i = 0; i < 2; i++)
#pragma unroll
            for (int j = 0; j < 4; j++)
#pragma unroll
                for (int q = 0; q < 4; q++) acc[i][j][q] = 0.f;

        {
            const float* As = sm + M5_AS;
            const float* Bs = sm + M5_BS;
            int lrow = lane & 7;
            int a_m = ((lane >> 3) & 1) * 8 + lrow;
            int a_k = (lane >> 4) * 4;
            int b_row8 = ((lane >> 4) & 1) * 8 + lrow;
            int b_k = ((lane >> 3) & 1) * 4;
#pragma unroll
            for (int ks = 0; ks < 4; ks++) {
                unsigned af[2][4], bf[4][2];
#pragma unroll
                for (int mi = 0; mi < 2; mi++) {
                    const float* p = As + (warp_m * 32 + mi * 16 + a_m) * ASTR + ks * 8 + a_k;
                    unsigned ad = (unsigned)__cvta_generic_to_shared(p);
                    asm volatile("ldmatrix.sync.aligned.m8n8.x4.shared.b16 {%0,%1,%2,%3}, [%4];"
                        : "=r"(af[mi][0]), "=r"(af[mi][1]), "=r"(af[mi][2]), "=r"(af[mi][3]) : "r"(ad));
                }
#pragma unroll
                for (int np = 0; np < 2; np++) {
                    const float* p = Bs + (warp_n * 32 + np * 16 + b_row8) * ASTR + ks * 8 + b_k;
                    unsigned ad = (unsigned)__cvta_generic_to_shared(p);
                    asm volatile("ldmatrix.sync.aligned.m8n8.x4.shared.b16 {%0,%1,%2,%3}, [%4];"
                        : "=r"(bf[np * 2][0]), "=r"(bf[np * 2][1]),
                          "=r"(bf[np * 2 + 1][0]), "=r"(bf[np * 2 + 1][1]) : "r"(ad));
                }
#pragma unroll
                for (int mi = 0; mi < 2; mi++)
#pragma unroll
                    for (int ni = 0; ni < 4; ni++) {
                        asm volatile(
                            "mma.sync.aligned.m16n8k8.row.col.f32.tf32.tf32.f32 "
                            "{%0,%1,%2,%3}, {%4,%5,%6,%7}, {%8,%9}, {%0,%1,%2,%3};"
                            : "+f"(acc[mi][ni][0]), "+f"(acc[mi][ni][1]),
                              "+f"(acc[mi][ni][2]), "+f"(acc[mi][ni][3])
                            : "r"(af[mi][0]), "r"(af[mi][1]), "r"(af[mi][2]), "r"(af[mi][3]),
                              "r"(bf[ni][0]), "r"(bf[ni][1]));
                    }
            }
        }

        const float* maa_f = (f == 0) ? mw : (f == 1) ? mk : (f == 2) ? mv : (f == 3) ? mr : mg;
        float* out_f       = (f == 0) ? xw : (f == 1) ? xk : (f == 2) ? xv : (f == 3) ? xr : xg;
#pragma unroll
        for (int mi = 0; mi < 2; mi++) {
#pragma unroll
            for (int ni = 0; ni < 4; ni++) {
                int ml = warp_m * 32 + mi * 16 + erow;
                int nl = warp_n * 32 + ni * 8 + ecol;
                int ng = n0 + nl;
                float2 xa = *(const float2*)(sm + M5_XS + ml * 72 + nl);
                float2 xb = *(const float2*)(sm + M5_XS + (ml + 8) * 72 + nl);
                float2 da = *(const float2*)(sm + M5_DS + ml * 72 + nl);
                float2 db = *(const float2*)(sm + M5_DS + (ml + 8) * 72 + nl);
                float2 ma = *(const float2*)(maa_f + ng);
                float2 v0, v1;
                v0.x = tf32r(xa.x + da.x * (ma.x + acc[mi][ni][0]));
                v0.y = tf32r(xa.y + da.y * (ma.y + acc[mi][ni][1]));
                v1.x = tf32r(xb.x + db.x * (ma.x + acc[mi][ni][2]));
                v1.y = tf32r(xb.y + db.y * (ma.y + acc[mi][ni][3]));
                *(float2*)(out_f + (size_t)(m0 + ml) * CDIM + ng) = v0;
                *(float2*)(out_f + (size_t)(m0 + ml + 8) * CDIM + ng) = v1;
            }
        }
        __syncthreads();
    }
}

// ---------------- ruk precompute: ruk[b][h][t] = sum_j r*u*k ----------------
__global__ void ruk_kernel(const float* __restrict__ r, const float* __restrict__ k,
                           const float* __restrict__ u, float* __restrict__ ruk)
{
    int gw = (blockIdx.x * blockDim.x + threadIdx.x) >> 5;
    int lane = threadIdx.x & 31;
    if (gw >= NR * NHEAD) return;
    int row = gw % NR, h = gw / NR;
    size_t o = (size_t)row * CDIM + h * HS;
    float p = r[o + lane] * u[h * HS + lane] * k[o + lane]
            + r[o + 32 + lane] * u[h * HS + 32 + lane] * k[o + 32 + lane];
#pragma unroll
    for (int s = 16; s; s >>= 1) p += __shfl_xor_sync(0xffffffffu, p, s);
    if (lane == 0) {
        int b = row / TDIM, t = row % TDIM;
        ruk[((size_t)(b * NHEAD + h)) * TDIM + t] = p;
    }
}

// ---------------- K4: WKV6 recurrence (streamlined) ----------------
__device__ __forceinline__ void wkv_issue(int ci, float* rsb, float* ksb,
        float* vsb, float* wsb,
        const float* rp, const float* kp, const float* vp, const float* wpp,
        size_t base, int tid)
{
#pragma unroll
    for (int p = 0; p < 2; p++) {
        int idx = tid + p * 256;
        int arr = idx >> 7;
        int rem = idx & 127;
        int tc = rem >> 4, c4 = (rem & 15) << 2;
        size_t gofs = base + (size_t)(ci * 8 + tc) * CDIM + c4;
        float* dst; const float* src;
        if (arr == 0)      { dst = rsb + tc * 64 + c4; src = rp  + gofs; }
        else if (arr == 1) { dst = ksb + tc * 64 + c4; src = kp  + gofs; }
        else if (arr == 2) { dst = vsb + tc * 64 + c4; src = vp  + gofs; }
        else               { dst = wsb + tc * 64 + c4; src = wpp + gofs; }
        cp16(dst, src);
    }
    asm volatile("cp.async.commit_group;" ::: "memory");
}

__global__ __launch_bounds__(256, 1) void wkv6_kernel(
    const float* __restrict__ rp, const float* __restrict__ kp,
    const float* __restrict__ vp, const float* __restrict__ wp_,   // decay factors
    const float* __restrict__ rukp, float* __restrict__ yp)
{
    __shared__ __align__(16) float rs[2][512], ks[2][512], vs[2][512], ws[2][512];
    int tid = threadIdx.x;
    int b = blockIdx.x / NHEAD, h = blockIdx.x % NHEAD;
    size_t base = (size_t)b * TDIM * CDIM + h * HS;
    size_t rukb = ((size_t)(b * NHEAD + h)) * TDIM;
    int i = tid >> 2, jq = tid & 3;

    float S[16];
#pragma unroll
    for (int q = 0; q < 16; q++) S[q] = 0.f;

    wkv_issue(0, rs[0], ks[0], vs[0], ws[0], rp, kp, vp, wp_, base, tid);

#pragma unroll 1
    for (int ci = 0; ci < TDIM / 8; ci++) {
        int buf = ci & 1;
        asm volatile("cp.async.wait_group 0;" ::: "memory");
        __syncthreads();
        if (ci + 1 < TDIM / 8) {
            int nb = buf ^ 1;
            wkv_issue(ci + 1, rs[nb], ks[nb], vs[nb], ws[nb], rp, kp, vp, wp_, base, tid);
        }
        float4 ruk0 = *(const float4*)(rukp + rukb + ci * 8);
        float4 ruk1 = *(const float4*)(rukp + rukb + ci * 8 + 4);
        float rukv[8] = {ruk0.x, ruk0.y, ruk0.z, ruk0.w, ruk1.x, ruk1.y, ruk1.z, ruk1.w};
#pragma unroll 1
        for (int tc = 0; tc < 8; tc++) {
            float vi = vs[buf][tc * 64 + i];
            const float4* r4 = (const float4*)&rs[buf][tc * 64 + jq * 16];
            const float4* k4 = (const float4*)&ks[buf][tc * 64 + jq * 16];
            const float4* w4 = (const float4*)&ws[buf][tc * 64 + jq * 16];
            float yps = 0.f;
#pragma unroll
            for (int q = 0; q < 4; q++) {
                float4 rv = r4[q], kv = k4[q], wv = w4[q];
                yps += rv.x * S[q * 4 + 0]; S[q * 4 + 0] = wv.x * S[q * 4 + 0] + kv.x * vi;
                yps += rv.y * S[q * 4 + 1]; S[q * 4 + 1] = wv.y * S[q * 4 + 1] + kv.y * vi;
                yps += rv.z * S[q * 4 + 2]; S[q * 4 + 2] = wv.z * S[q * 4 + 2] + kv.z * vi;
                yps += rv.w * S[q * 4 + 3]; S[q * 4 + 3] = wv.w * S[q * 4 + 3] + kv.w * vi;
            }
            yps += __shfl_xor_sync(0xffffffffu, yps, 1);
            yps += __shfl_xor_sync(0xffffffffu, yps, 2);
            if (jq == 0)
                yp[base + (size_t)(ci * 8 + tc) * CDIM + i] = yps + vi * rukv[tc];
        }
    }
}

// ---------------- K5: per-head GroupNorm * g ----------------
__global__ void gn_mul_kernel(const float* __restrict__ y,
                              const float* __restrict__ lw, const float* __restrict__ lb,
                              const float* __restrict__ g, float* __restrict__ out)
{
    int row = blockIdx.x;
    int warp = threadIdx.x >> 5, lane = threadIdx.x & 31;
    size_t o = (size_t)row * CDIM + warp * HS;
    float v0 = y[o + lane], v1 = y[o + 32 + lane];
    float s = v0 + v1, ss = v0 * v0 + v1 * v1;
#pragma unroll
    for (int off = 16; off; off >>= 1) {
        s  += __shfl_xor_sync(0xffffffffu, s,  off);
        ss += __shfl_xor_sync(0xffffffffu, ss, off);
    }
    float mean = s * (1.f / HS);
    float var  = ss * (1.f / HS) - mean * mean;
    float inv  = rsqrtf(var + 1e-5f);
    int c0 = warp * HS + lane, c1 = c0 + 32;
    float n0 = (v0 - mean) * inv * lw[c0] + lb[c0];
    float n1 = (v1 - mean) * inv * lw[c1] + lb[c1];
    out[o + lane]      = tf32r(n0 * g[o + lane]);
    out[o + 32 + lane] = tf32r(n1 * g[o + 32 + lane]);
}

// ---------------- launcher ----------------
extern "C" void kernel_launch(void* const* d_in, const int* in_sizes, int n_in,
                              void* d_out, int out_size)
{
    const float* x          = (const float*)d_in[0];
    const float* W_r        = (const float*)d_in[1];
    const float* W_k        = (const float*)d_in[2];
    const float* W_v        = (const float*)d_in[3];
    const float* W_g        = (const float*)d_in[4];
    const float* W_o        = (const float*)d_in[5];
    const float* maa_x      = (const float*)d_in[6];
    const float* maa_w      = (const float*)d_in[7];
    const float* maa_k      = (const float*)d_in[8];
    const float* maa_v      = (const float*)d_in[9];
    const float* maa_r      = (const float*)d_in[10];
    const float* maa_g      = (const float*)d_in[11];
    const float* maa_w1     = (const float*)d_in[12];
    const float* maa_w2     = (const float*)d_in[13];
    const float* time_decay = (const float*)d_in[14];
    const float* dec_w1     = (const float*)d_in[15];
    const float* dec_w2     = (const float*)d_in[16];
    const float* faaaa      = (const float*)d_in[17];
    const float* ln_w       = (const float*)d_in[18];
    const float* ln_b       = (const float*)d_in[19];
    float* out = (float*)d_out;

    float *xx, *xxx, *tb, *xw, *xk, *xv, *xr, *xg, *rb, *kb, *vb, *gb, *h1, *wb, *yb, *yg, *rukb, *Wc, *Wt, *Wm;
    cudaGetSymbolAddress((void**)&xx,   g_xx);
    cudaGetSymbolAddress((void**)&xxx,  g_xxx);
    cudaGetSymbolAddress((void**)&tb,   g_t);
    cudaGetSymbolAddress((void**)&xw,   g_xw);
    cudaGetSymbolAddress((void**)&xk,   g_xk);
    cudaGetSymbolAddress((void**)&xv,   g_xv);
    cudaGetSymbolAddress((void**)&xr,   g_xr);
    cudaGetSymbolAddress((void**)&xg,   g_xg);
    cudaGetSymbolAddress((void**)&rb,   g_r);
    cudaGetSymbolAddress((void**)&kb,   g_k);
    cudaGetSymbolAddress((void**)&vb,   g_v);
    cudaGetSymbolAddress((void**)&gb,   g_g);
    cudaGetSymbolAddress((void**)&h1,   g_h1);
    cudaGetSymbolAddress((void**)&wb,   g_w);
    cudaGetSymbolAddress((void**)&yb,   g_y);
    cudaGetSymbolAddress((void**)&yg,   g_yg);
    cudaGetSymbolAddress((void**)&rukb, g_ruk);
    cudaGetSymbolAddress((void**)&Wc,   g_Wc);
    cudaGetSymbolAddress((void**)&Wt,   g_Wt);
    cudaGetSymbolAddress((void**)&Wm,   g_Wm);

    const int NW = CDIM * CDIM;
    float* Wr_c = Wc + 0 * NW;
    float* Wk_c = Wc + 1 * NW;
    float* Wv_c = Wc + 2 * NW;
    float* Wg_c = Wc + 3 * NW;
    float* Wo_c = Wc + 4 * NW;
    float* W1t  = Wt;
    float* D1t  = Wt + 160 * CDIM;
    float* D2t  = Wt + 160 * CDIM + 64 * CDIM;

    cudaFuncSetAttribute(gemm_tf32_kernel<0>, cudaFuncAttributeMaxDynamicSharedMemorySize, GT_SMEM);
    cudaFuncSetAttribute(gemm_tf32_kernel<4>, cudaFuncAttributeMaxDynamicSharedMemorySize, GT_SMEM);
    cudaFuncSetAttribute(gemm_tf32_batch5_kernel, cudaFuncAttributeMaxDynamicSharedMemorySize, GT_SMEM);
    cudaFuncSetAttribute(mix5g_kernel, cudaFuncAttributeMaxDynamicSharedMemorySize, M5_SMEM);

    prep_shift_kernel<<<(PRE5 + 255) / 256, 256>>>(W_r, W_k, W_v, W_g, W_o,          // 1
        maa_w1, dec_w1, dec_w2, maa_w2, Wc, Wt, Wm, x, maa_x, xx, xxx);
    {                                                                                 // 2
        dim3 grid(2, NR / 128);
        gemm_tf32_kernel<4><<<grid, 256, GT_SMEM>>>(xxx, W1t, tb, 160, CDIM, nullptr);
    }
    {                                                                                 // 3
        dim3 grid(CDIM / 64, NR / 128);
        mix5g_kernel<<<grid, 256, M5_SMEM>>>(tb, Wm, x, xx,
            maa_w, maa_k, maa_v, maa_r, maa_g, xw, xk, xv, xr, xg);
    }
    {                                                                                 // 4
        dim3 grid(1, NR / 128);
        gemm_tf32_kernel<4><<<grid, 256, GT_SMEM>>>(xw, D1t, h1, 64, CDIM, nullptr);
    }
    {                                                                                 // 5
        dim3 grid(6, NR / 128, 5);
        gemm_tf32_batch5_kernel<<<grid, 256, GT_SMEM>>>(
            xr, xk, xv, xg, h1, Wr_c, Wk_c, Wv_c, Wg_c, D2t,
            rb, kb, vb, gb, wb, time_decay);
    }
    ruk_kernel<<<(NR * NHEAD * 32 + 255) / 256, 256>>>(rb, kb, faaaa, rukb);          // 6
    wkv6_kernel<<<8 * NHEAD, 256>>>(rb, kb, vb, wb, rukb, yb);                        // 7
    gn_mul_kernel<<<NR, 384>>>(yb, ln_w, ln_b, gb, yg);                               // 8
    {                                                                                 // 9
        dim3 gcc(6, NR / 128);
        gemm_tf32_kernel<0><<<gcc, 256, GT_SMEM>>>(yg, Wo_c, out, CDIM, CDIM, nullptr);
    }
}

// round 15
// speedup vs baseline: 1.0772x; 1.0026x over previous
#include <cuda_runtime.h>
#include <math.h>

#define TDIM 1024
#define CDIM 768
#define PH 32
#define PW 32
#define NHEAD 12
#define HS 64
#define NR (8*1024)

__device__ float g_xx [NR*CDIM];
__device__ float g_xxx[NR*CDIM];
__device__ float g_t  [NR*160];
__device__ float g_xw [NR*CDIM];
__device__ float g_xk [NR*CDIM];
__device__ float g_xv [NR*CDIM];
__device__ float g_xr [NR*CDIM];
__device__ float g_xg [NR*CDIM];
__device__ float g_r  [NR*CDIM];
__device__ float g_k  [NR*CDIM];
__device__ float g_v  [NR*CDIM];
__device__ float g_g  [NR*CDIM];
__device__ float g_h1 [NR*64];
__device__ float g_w  [NR*CDIM];
__device__ float g_y  [NR*CDIM];
__device__ float g_yg [NR*CDIM];
__device__ float g_ruk[NR*NHEAD];
__device__ float g_Wc [5*CDIM*CDIM];
__device__ float g_Wt [160*CDIM + 64*CDIM + CDIM*64];
__device__ float g_Wm [5*CDIM*32];

__device__ __forceinline__ float tf32r(float x) {
    unsigned u;
    asm("cvt.rna.tf32.f32 %0, %1;" : "=r"(u) : "f"(x));
    return __uint_as_float(u);
}
__device__ __forceinline__ void cp16(void* dst, const void* src) {
    unsigned d = (unsigned)__cvta_generic_to_shared(dst);
    asm volatile("cp.async.cg.shared.global [%0], [%1], 16;" :: "r"(d), "l"(src) : "memory");
}
__device__ __forceinline__ void cp16z(void* dst, const void* src, int sz) {
    unsigned d = (unsigned)__cvta_generic_to_shared(dst);
    asm volatile("cp.async.cg.shared.global [%0], [%1], 16, %2;" :: "r"(d), "l"(src), "r"(sz) : "memory");
}

// ---------------- fused weight prep + q_shift mix (one launch) ----------------
#define NW_ (CDIM*CDIM)
#define PRE0 (5*NW_)
#define PRE1 (PRE0 + 160*CDIM)
#define PRE2 (PRE1 + 64*CDIM)
#define PRE3 (PRE2 + CDIM*64)
#define PRE4 (PRE3 + 5*CDIM*32)
#define C4 (CDIM/4)
#define PRE5 (PRE4 + NR*C4)
__global__ void prep_shift_kernel(const float* __restrict__ w0, const float* __restrict__ w1,
                                  const float* __restrict__ w2, const float* __restrict__ w3,
                                  const float* __restrict__ w4,
                                  const float* __restrict__ maa_w1, const float* __restrict__ dec_w1,
                                  const float* __restrict__ dec_w2, const float* __restrict__ maa_w2,
                                  float* __restrict__ Wc, float* __restrict__ Wt, float* __restrict__ Wm,
                                  const float* __restrict__ x, const float* __restrict__ maa_x,
                                  float* __restrict__ xx, float* __restrict__ xxx)
{
    int idx = blockIdx.x * blockDim.x + threadIdx.x;
    if (idx >= PRE5) return;
    if (idx < PRE0) {
        int m = idx / NW_, r = idx % NW_;
        const float* src = (m == 0) ? w0 : (m == 1) ? w1 : (m == 2) ? w2 : (m == 3) ? w3 : w4;
        Wc[idx] = tf32r(src[r]);
    } else if (idx < PRE1) {
        int o = idx - PRE0;
        int n = o / CDIM, k = o % CDIM;
        Wt[o] = tf32r(maa_w1[k * 160 + n]);
    } else if (idx < PRE2) {
        int o = idx - PRE1;
        int n = o / CDIM, k = o % CDIM;
        Wt[160 * CDIM + o] = tf32r(dec_w1[k * 64 + n]);
    } else if (idx < PRE3) {
        int o = idx - PRE2;
        int n = o / 64, k = o % 64;
        Wt[160 * CDIM + 64 * CDIM + o] = tf32r(dec_w2[k * CDIM + n]);
    } else if (idx < PRE4) {
        int o = idx - PRE3;
        int f = o / (CDIM * 32);
        int rem = o % (CDIM * 32);
        int c = rem >> 5, j = rem & 31;
        Wm[o] = tf32r(maa_w2[(f * 32 + j) * CDIM + c]);
    } else {
        int e = idx - PRE4;
        int c4 = e % C4;
        int t = (e / C4) % TDIM;
        int b = e / (C4 * TDIM);
        int d4 = c4 & 15;
        int hh = t >> 5, ww = t & 31;
        int st = -1;
        if (d4 < 4)       { if (ww >= 1)      st = t - 1;  }
        else if (d4 < 8)  { if (ww < PW - 1)  st = t + 1;  }
        else if (d4 < 12) { if (hh >= 1)      st = t - PW; }
        else              { if (hh < PH - 1)  st = t + PW; }
        float4 sh = make_float4(0.f, 0.f, 0.f, 0.f);
        if (st >= 0)
            sh = *(const float4*)(x + (((size_t)b * TDIM + st) * C4 + c4) * 4);
        float4 xv = *(const float4*)(x + (size_t)e * 4);
        float4 mm = *(const float4*)(maa_x + c4 * 4);
        float4 dd, ox;
        dd.x = sh.x - xv.x; dd.y = sh.y - xv.y; dd.z = sh.z - xv.z; dd.w = sh.w - xv.w;
        ox.x = tf32r(xv.x + dd.x * mm.x);
        ox.y = tf32r(xv.y + dd.y * mm.y);
        ox.z = tf32r(xv.z + dd.z * mm.z);
        ox.w = tf32r(xv.w + dd.w * mm.w);
        *(float4*)(xx + (size_t)e * 4) = dd;
        *(float4*)(xxx + (size_t)e * 4) = ox;
    }
}

// ---------------- mma.sync tf32 GEMM (2-stage, 128-row tile) ----------------
#define ASTR   36
#define ASZ    (128*ASTR)
#define GT_SMEM (4*ASZ*4)   // 73728 B

template<int EPI>
__device__ __forceinline__ float epi_f(float a, const float* bias, int n) {
    if (EPI == 1) return tanhf(a);
    if (EPI == 2) return fmaxf(a, 0.f);
    if (EPI == 3) return a + bias[n];
    if (EPI == 4) return tf32r(tanhf(a));
    if (EPI == 5) return expf(-expf(a + bias[n]));
    return a;
}

__device__ __forceinline__ void gt_issue(float* sm, const float* __restrict__ A,
                                         const float* __restrict__ Bm,
                                         int m0, int n0, int it, int tid, int N, int K)
{
    int s = it & 1;
    float* As = sm + s * ASZ;
    float* Bs = sm + 2 * ASZ + s * ASZ;
    int k0 = it * 32;
#pragma unroll
    for (int p = 0; p < 4; p++) {
        int c = tid + p * 256;
        int row = c >> 3, kc = (c & 7) << 2;
        cp16(As + row * ASTR + kc, A + (size_t)(m0 + row) * K + k0 + kc);
    }
#pragma unroll
    for (int p = 0; p < 4; p++) {
        int c = tid + p * 256;
        int row = c >> 3, kc = (c & 7) << 2;
        int valid = (n0 + row) < N;
        const float* src = Bm + (valid ? ((size_t)(n0 + row) * K + k0 + kc) : 0);
        cp16z(Bs + row * ASTR + kc, src, valid ? 16 : 0);
    }
    asm volatile("cp.async.commit_group;" ::: "memory");
}

__device__ __forceinline__ void gt_mma_stage(const float* As, const float* Bs,
                                             int warp_m, int warp_n, int lane,
                                             float acc[4][4][4])
{
    int lrow = lane & 7;
    int a_m = ((lane >> 3) & 1) * 8 + lrow;
    int a_k = (lane >> 4) * 4;
    int b_row8 = ((lane >> 4) & 1) * 8 + lrow;
    int b_k = ((lane >> 3) & 1) * 4;
#pragma unroll
    for (int ks = 0; ks < 4; ks++) {
        unsigned af[4][4], bf[4][2];
#pragma unroll
        for (int mi = 0; mi < 4; mi++) {
            const float* p = As + (warp_m * 64 + mi * 16 + a_m) * ASTR + ks * 8 + a_k;
            unsigned ad = (unsigned)__cvta_generic_to_shared(p);
            asm volatile("ldmatrix.sync.aligned.m8n8.x4.shared.b16 {%0,%1,%2,%3}, [%4];"
                : "=r"(af[mi][0]), "=r"(af[mi][1]), "=r"(af[mi][2]), "=r"(af[mi][3]) : "r"(ad));
        }
#pragma unroll
        for (int np = 0; np < 2; np++) {
            const float* p = Bs + (warp_n * 32 + np * 16 + b_row8) * ASTR + ks * 8 + b_k;
            unsigned ad = (unsigned)__cvta_generic_to_shared(p);
            asm volatile("ldmatrix.sync.aligned.m8n8.x4.shared.b16 {%0,%1,%2,%3}, [%4];"
                : "=r"(bf[np * 2][0]), "=r"(bf[np * 2][1]),
                  "=r"(bf[np * 2 + 1][0]), "=r"(bf[np * 2 + 1][1]) : "r"(ad));
        }
#pragma unroll
        for (int mi = 0; mi < 4; mi++)
#pragma unroll
            for (int ni = 0; ni < 4; ni++) {
                asm volatile(
                    "mma.sync.aligned.m16n8k8.row.col.f32.tf32.tf32.f32 "
                    "{%0,%1,%2,%3}, {%4,%5,%6,%7}, {%8,%9}, {%0,%1,%2,%3};"
                    : "+f"(acc[mi][ni][0]), "+f"(acc[mi][ni][1]),
                      "+f"(acc[mi][ni][2]), "+f"(acc[mi][ni][3])
                    : "r"(af[mi][0]), "r"(af[mi][1]), "r"(af[mi][2]), "r"(af[mi][3]),
                      "r"(bf[ni][0]), "r"(bf[ni][1]));
            }
    }
}

template<int EPI, bool RELU_RT>
__device__ __forceinline__ void gt_body(const float* __restrict__ A, const float* __restrict__ Bm,
                                        float* __restrict__ Cm, int N, int K,
                                        const float* __restrict__ bias, int relu_flag)
{
    extern __shared__ __align__(16) float sm[];
    int tid = threadIdx.x;
    int lane = tid & 31, warp = tid >> 5;
    int warp_m = warp >> 2, warp_n = warp & 3;
    int m0 = blockIdx.y * 128, n0 = blockIdx.x * 128;

    float acc[4][4][4];
#pragma unroll
    for (int i = 0; i < 4; i++)
#pragma unroll
        for (int j = 0; j < 4; j++)
#pragma unroll
            for (int q = 0; q < 4; q++) acc[i][j][q] = 0.f;

    gt_issue(sm, A, Bm, m0, n0, 0, tid, N, K);

    const int NIT = K / 32;
#pragma unroll 1
    for (int it = 0; it < NIT; it++) {
        if (it + 1 < NIT) {
            gt_issue(sm, A, Bm, m0, n0, it + 1, tid, N, K);
            asm volatile("cp.async.wait_group 1;" ::: "memory");
        } else {
            asm volatile("cp.async.wait_group 0;" ::: "memory");
        }
        __syncthreads();
        int s = it & 1;
        gt_mma_stage(sm + s * ASZ, sm + 2 * ASZ + s * ASZ, warp_m, warp_n, lane, acc);
        __syncthreads();
    }

    int erow = lane >> 2, ecol = (lane & 3) * 2;
#pragma unroll
    for (int mi = 0; mi < 4; mi++) {
#pragma unroll
        for (int ni = 0; ni < 4; ni++) {
            int m = m0 + warp_m * 64 + mi * 16 + erow;
            int n = n0 + warp_n * 32 + ni * 8 + ecol;
            if (n < N) {
                float2 v0, v1;
                v0.x = epi_f<EPI>(acc[mi][ni][0], bias, n);
                v0.y = epi_f<EPI>(acc[mi][ni][1], bias, n + 1);
                v1.x = epi_f<EPI>(acc[mi][ni][2], bias, n);
                v1.y = epi_f<EPI>(acc[mi][ni][3], bias, n + 1);
                if (RELU_RT && relu_flag) {
                    v0.x = fmaxf(v0.x, 0.f); v0.y = fmaxf(v0.y, 0.f);
                    v1.x = fmaxf(v1.x, 0.f); v1.y = fmaxf(v1.y, 0.f);
                }
                *(float2*)(Cm + (size_t)m * N + n) = v0;
                *(float2*)(Cm + (size_t)(m + 8) * N + n) = v1;
            }
        }
    }
}

template<int EPI>
__global__ __launch_bounds__(256, 2) void gemm_tf32_kernel(
    const float* __restrict__ A, const float* __restrict__ Bm,
    float* __restrict__ Cm, int N, int K, const float* __restrict__ bias)
{
    gt_body<EPI, false>(A, Bm, Cm, N, K, bias, 0);
}

__global__ __launch_bounds__(256, 2) void gemm_tf32_batch5_kernel(
    const float* __restrict__ a0, const float* __restrict__ a1,
    const float* __restrict__ a2, const float* __restrict__ a3,
    const float* __restrict__ a4,
    const float* __restrict__ b0, const float* __restrict__ b1,
    const float* __restrict__ b2, const float* __restrict__ b3,
    const float* __restrict__ b4,
    float* __restrict__ c0, float* __restrict__ c1,
    float* __restrict__ c2, float* __restrict__ c3,
    float* __restrict__ c4,
    const float* __restrict__ bias4)
{
    int z = blockIdx.z;
    if (z < 4) {
        const float* A  = (z == 0) ? a0 : (z == 1) ? a1 : (z == 2) ? a2 : a3;
        const float* Bm = (z == 0) ? b0 : (z == 1) ? b1 : (z == 2) ? b2 : b3;
        float* Cm       = (z == 0) ? c0 : (z == 1) ? c1 : (z == 2) ? c2 : c3;
        gt_body<0, true>(A, Bm, Cm, CDIM, CDIM, nullptr, z == 3);
    } else {
        gt_body<5, false>(a4, b4, c4, CDIM, 64, bias4, 0);
    }
}

// ---------------- 64-row-tile GEMM for skinny-M-parallelism launches ----------------
// layout: [A s0][A s1][B s0][B s1]; A 64*ASTR, B 128*ASTR per stage
#define M64_ASZ (64*ASTR)
#define M64_BOF (2*M64_ASZ)
#define M64_SMEM ((2*M64_ASZ + 2*ASZ)*4)   // 55296 B

__device__ __forceinline__ void gt64_issue(float* sm, const float* __restrict__ A,
                                           const float* __restrict__ Bm,
                                           int m0, int n0, int it, int tid, int N, int K)
{
    int s = it & 1;
    float* As = sm + s * M64_ASZ;
    float* Bs = sm + M64_BOF + s * ASZ;
    int k0 = it * 32;
#pragma unroll
    for (int p = 0; p < 2; p++) {
        int c = tid + p * 256;
        int row = c >> 3, kc = (c & 7) << 2;
        cp16(As + row * ASTR + kc, A + (size_t)(m0 + row) * K + k0 + kc);
    }
#pragma unroll
    for (int p = 0; p < 4; p++) {
        int c = tid + p * 256;
        int row = c >> 3, kc = (c & 7) << 2;
        int valid = (n0 + row) < N;
        const float* src = Bm + (valid ? ((size_t)(n0 + row) * K + k0 + kc) : 0);
        cp16z(Bs + row * ASTR + kc, src, valid ? 16 : 0);
    }
    asm volatile("cp.async.commit_group;" ::: "memory");
}

template<int EPI>
__global__ __launch_bounds__(256, 2) void gemm_tf32_m64_kernel(
    const float* __restrict__ A, const float* __restrict__ Bm,
    float* __restrict__ Cm, int N, int K, const float* __restrict__ bias)
{
    extern __shared__ __align__(16) float sm[];
    int tid = threadIdx.x;
    int lane = tid & 31, warp = tid >> 5;
    int warp_m = warp >> 2, warp_n = warp & 3;   // 2 x 4, warp tile 32x32
    int m0 = blockIdx.y * 64, n0 = blockIdx.x * 128;

    float acc[2][4][4];
#pragma unroll
    for (int i = 0; i < 2; i++)
#pragma unroll
        for (int j = 0; j < 4; j++)
#pragma unroll
            for (int q = 0; q < 4; q++) acc[i][j][q] = 0.f;

    gt64_issue(sm, A, Bm, m0, n0, 0, tid, N, K);

    int lrow = lane & 7;
    int a_m = ((lane >> 3) & 1) * 8 + lrow;
    int a_k = (lane >> 4) * 4;
    int b_row8 = ((lane >> 4) & 1) * 8 + lrow;
    int b_k = ((lane >> 3) & 1) * 4;

    const int NIT = K / 32;
#pragma unroll 1
    for (int it = 0; it < NIT; it++) {
        if (it + 1 < NIT) {
            gt64_issue(sm, A, Bm, m0, n0, it + 1, tid, N, K);
            asm volatile("cp.async.wait_group 1;" ::: "memory");
        } else {
            asm volatile("cp.async.wait_group 0;" ::: "memory");
        }
        __syncthreads();
        int s = it & 1;
        const float* As = sm + s * M64_ASZ;
        const float* Bs = sm + M64_BOF + s * ASZ;
#pragma unroll
        for (int ks = 0; ks < 4; ks++) {
            unsigned af[2][4], bf[4][2];
#pragma unroll
            for (int mi = 0; mi < 2; mi++) {
                const float* p = As + (warp_m * 32 + mi * 16 + a_m) * ASTR + ks * 8 + a_k;
                unsigned ad = (unsigned)__cvta_generic_to_shared(p);
                asm volatile("ldmatrix.sync.aligned.m8n8.x4.shared.b16 {%0,%1,%2,%3}, [%4];"
                    : "=r"(af[mi][0]), "=r"(af[mi][1]), "=r"(af[mi][2]), "=r"(af[mi][3]) : "r"(ad));
            }
#pragma unroll
            for (int np = 0; np < 2; np++) {
                const float* p = Bs + (warp_n * 32 + np * 16 + b_row8) * ASTR + ks * 8 + b_k;
                unsigned ad = (unsigned)__cvta_generic_to_shared(p);
                asm volatile("ldmatrix.sync.aligned.m8n8.x4.shared.b16 {%0,%1,%2,%3}, [%4];"
                    : "=r"(bf[np * 2][0]), "=r"(bf[np * 2][1]),
                      "=r"(bf[np * 2 + 1][0]), "=r"(bf[np * 2 + 1][1]) : "r"(ad));
            }
#pragma unroll
            for (int mi = 0; mi < 2; mi++)
#pragma unroll
                for (int ni = 0; ni < 4; ni++) {
                    asm volatile(
                        "mma.sync.aligned.m16n8k8.row.col.f32.tf32.tf32.f32 "
                        "{%0,%1,%2,%3}, {%4,%5,%6,%7}, {%8,%9}, {%0,%1,%2,%3};"
                        : "+f"(acc[mi][ni][0]), "+f"(acc[mi][ni][1]),
                          "+f"(acc[mi][ni][2]), "+f"(acc[mi][ni][3])
                        : "r"(af[mi][0]), "r"(af[mi][1]), "r"(af[mi][2]), "r"(af[mi][3]),
                          "r"(bf[ni][0]), "r"(bf[ni][1]));
                }
        }
        __syncthreads();
    }

    int erow = lane >> 2, ecol = (lane & 3) * 2;
#pragma unroll
    for (int mi = 0; mi < 2; mi++) {
#pragma unroll
        for (int ni = 0; ni < 4; ni++) {
            int m = m0 + warp_m * 32 + mi * 16 + erow;
            int n = n0 + warp_n * 32 + ni * 8 + ecol;
            if (n < N) {
                float2 v0, v1;
                v0.x = epi_f<EPI>(acc[mi][ni][0], bias, n);
                v0.y = epi_f<EPI>(acc[mi][ni][1], bias, n + 1);
                v1.x = epi_f<EPI>(acc[mi][ni][2], bias, n);
                v1.y = epi_f<EPI>(acc[mi][ni][3], bias, n + 1);
                *(float2*)(Cm + (size_t)m * N + n) = v0;
                *(float2*)(Cm + (size_t)(m + 8) * N + n) = v1;
            }
        }
    }
}

// ---------------- mix5 GEMM, 128x64 tile, smem-cached x/xx ----------------
#define M5_XS 0
#define M5_DS 9216
#define M5_AS 18432
#define M5_BS 23040
#define M5_SMEM (25344*4)

__global__ __launch_bounds__(256, 2) void mix5g_kernel(
    const float* __restrict__ tb, const float* __restrict__ Wm,
    const float* __restrict__ x, const float* __restrict__ xx,
    const float* __restrict__ mw, const float* __restrict__ mk,
    const float* __restrict__ mv, const float* __restrict__ mr,
    const float* __restrict__ mg,
    float* __restrict__ xw, float* __restrict__ xk, float* __restrict__ xv,
    float* __restrict__ xr, float* __restrict__ xg)
{
    extern __shared__ __align__(16) float sm[];
    int tid = threadIdx.x;
    int lane = tid & 31, warp = tid >> 5;
    int warp_m = warp >> 1, warp_n = warp & 1;
    int m0 = blockIdx.y * 128, n0 = blockIdx.x * 64;
    int erow = lane >> 2, ecol = (lane & 3) * 2;

#pragma unroll
    for (int p = 0; p < 8; p++) {
        int c = tid + p * 256;
        int row = c >> 4, c16 = c & 15;
        cp16(sm + M5_XS + row * 72 + c16 * 4, x  + (size_t)(m0 + row) * CDIM + n0 + c16 * 4);
        cp16(sm + M5_DS + row * 72 + c16 * 4, xx + (size_t)(m0 + row) * CDIM + n0 + c16 * 4);
    }
    asm volatile("cp.async.commit_group;" ::: "memory");

#pragma unroll 1
    for (int f = 0; f < 5; f++) {
#pragma unroll
        for (int p = 0; p < 4; p++) {
            int c = tid + p * 256;
            int row = c >> 3, kc = (c & 7) << 2;
            cp16(sm + M5_AS + row * ASTR + kc, tb + (size_t)(m0 + row) * 160 + f * 32 + kc);
        }
#pragma unroll
        for (int p = 0; p < 2; p++) {
            int c = tid + p * 256;
            int row = c >> 3, kc = (c & 7) << 2;
            cp16(sm + M5_BS + row * ASTR + kc, Wm + (size_t)f * CDIM * 32 + (size_t)(n0 + row) * 32 + kc);
        }
        asm volatile("cp.async.commit_group;" ::: "memory");
        asm volatile("cp.async.wait_group 0;" ::: "memory");
        __syncthreads();

        float acc[2][4][4];
#pragma unroll
        for (int i = 0; i < 2; i++)
#pragma unroll
            for (int j = 0; j < 4; j++)
#pragma unroll
                for (int q = 0; q < 4; q++) acc[i][j][q] = 0.f;

        {
            const float* As = sm + M5_AS;
            const float* Bs = sm + M5_BS;
            int lrow = lane & 7;
            int a_m = ((lane >> 3) & 1) * 8 + lrow;
            int a_k = (lane >> 4) * 4;
            int b_row8 = ((lane >> 4) & 1) * 8 + lrow;
            int b_k = ((lane >> 3) & 1) * 4;
#pragma unroll
            for (int ks = 0; ks < 4; ks++) {
                unsigned af[2][4], bf[4][2];
#pragma unroll
                for (int mi = 0; mi < 2; mi++) {
                    const float* p = As + (warp_m * 32 + mi * 16 + a_m) * ASTR + ks * 8 + a_k;
                    unsigned ad = (unsigned)__cvta_generic_to_shared(p);
                    asm volatile("ldmatrix.sync.aligned.m8n8.x4.shared.b16 {%0,%1,%2,%3}, [%4];"
                        : "=r"(af[mi][0]), "=r"(af[mi][1]), "=r"(af[mi][2]), "=r"(af[mi][3]) : "r"(ad));
                }
#pragma unroll
                for (int np = 0; np < 2; np++) {
                    const float* p = Bs + (warp_n * 32 + np * 16 + b_row8) * ASTR + ks * 8 + b_k;
                    unsigned ad = (unsigned)__cvta_generic_to_shared(p);
                    asm volatile("ldmatrix.sync.aligned.m8n8.x4.shared.b16 {%0,%1,%2,%3}, [%4];"
                        : "=r"(bf[np * 2][0]), "=r"(bf[np * 2][1]),
                          "=r"(bf[np * 2 + 1][0]), "=r"(bf[np * 2 + 1][1]) : "r"(ad));
                }
#pragma unroll
                for (int mi = 0; mi < 2; mi++)
#pragma unroll
                    for (int ni = 0; ni < 4; ni++) {
                        asm volatile(
                            "mma.sync.aligned.m16n8k8.row.col.f32.tf32.tf32.f32 "
                            "{%0,%1,%2,%3}, {%4,%5,%6,%7}, {%8,%9}, {%0,%1,%2,%3};"
                            : "+f"(acc[mi][ni][0]), "+f"(acc[mi][ni][1]),
                              "+f"(acc[mi][ni][2]), "+f"(acc[mi][ni][3])
                            : "r"(af[mi][0]), "r"(af[mi][1]), "r"(af[mi][2]), "r"(af[mi][3]),
                              "r"(bf[ni][0]), "r"(bf[ni][1]));
                    }
            }
        }

        const float* maa_f = (f == 0) ? mw : (f == 1) ? mk : (f == 2) ? mv : (f == 3) ? mr : mg;
        float* out_f       = (f == 0) ? xw : (f == 1) ? xk : (f == 2) ? xv : (f == 3) ? xr : xg;
#pragma unroll
        for (int mi = 0; mi < 2; mi++) {
#pragma unroll
            for (int ni = 0; ni < 4; ni++) {
                int ml = warp_m * 32 + mi * 16 + erow;
                int nl = warp_n * 32 + ni * 8 + ecol;
                int ng = n0 + nl;
                float2 xa = *(const float2*)(sm + M5_XS + ml * 72 + nl);
                float2 xb = *(const float2*)(sm + M5_XS + (ml + 8) * 72 + nl);
                float2 da = *(const float2*)(sm + M5_DS + ml * 72 + nl);
                float2 db = *(const float2*)(sm + M5_DS + (ml + 8) * 72 + nl);
                float2 ma = *(const float2*)(maa_f + ng);
                float2 v0, v1;
                v0.x = tf32r(xa.x + da.x * (ma.x + acc[mi][ni][0]));
                v0.y = tf32r(xa.y + da.y * (ma.y + acc[mi][ni][1]));
                v1.x = tf32r(xb.x + db.x * (ma.x + acc[mi][ni][2]));
                v1.y = tf32r(xb.y + db.y * (ma.y + acc[mi][ni][3]));
                *(float2*)(out_f + (size_t)(m0 + ml) * CDIM + ng) = v0;
                *(float2*)(out_f + (size_t)(m0 + ml + 8) * CDIM + ng) = v1;
            }
        }
        __syncthreads();
    }
}

// ---------------- ruk precompute ----------------
__global__ void ruk_kernel(const float* __restrict__ r, const float* __restrict__ k,
                           const float* __restrict__ u, float* __restrict__ ruk)
{
    int gw = (blockIdx.x * blockDim.x + threadIdx.x) >> 5;
    int lane = threadIdx.x & 31;
    if (gw >= NR * NHEAD) return;
    int row = gw % NR, h = gw / NR;
    size_t o = (size_t)row * CDIM + h * HS;
    float p = r[o + lane] * u[h * HS + lane] * k[o + lane]
            + r[o + 32 + lane] * u[h * HS + 32 + lane] * k[o + 32 + lane];
#pragma unroll
    for (int s = 16; s; s >>= 1) p += __shfl_xor_sync(0xffffffffu, p, s);
    if (lane == 0) {
        int b = row / TDIM, t = row % TDIM;
        ruk[((size_t)(b * NHEAD + h)) * TDIM + t] = p;
    }
}

// ---------------- K4: WKV6 recurrence (streamlined) ----------------
__device__ __forceinline__ void wkv_issue(int ci, float* rsb, float* ksb,
        float* vsb, float* wsb,
        const float* rp, const float* kp, const float* vp, const float* wpp,
        size_t base, int tid)
{
#pragma unroll
    for (int p = 0; p < 2; p++) {
        int idx = tid + p * 256;
        int arr = idx >> 7;
        int rem = idx & 127;
        int tc = rem >> 4, c4 = (rem & 15) << 2;
        size_t gofs = base + (size_t)(ci * 8 + tc) * CDIM + c4;
        float* dst; const float* src;
        if (arr == 0)      { dst = rsb + tc * 64 + c4; src = rp  + gofs; }
        else if (arr == 1) { dst = ksb + tc * 64 + c4; src = kp  + gofs; }
        else if (arr == 2) { dst = vsb + tc * 64 + c4; src = vp  + gofs; }
        else               { dst = wsb + tc * 64 + c4; src = wpp + gofs; }
        cp16(dst, src);
    }
    asm volatile("cp.async.commit_group;" ::: "memory");
}

__global__ __launch_bounds__(256, 1) void wkv6_kernel(
    const float* __restrict__ rp, const float* __restrict__ kp,
    const float* __restrict__ vp, const float* __restrict__ wp_,
    const float* __restrict__ rukp, float* __restrict__ yp)
{
    __shared__ __align__(16) float rs[2][512], ks[2][512], vs[2][512], ws[2][512];
    int tid = threadIdx.x;
    int b = blockIdx.x / NHEAD, h = blockIdx.x % NHEAD;
    size_t base = (size_t)b * TDIM * CDIM + h * HS;
    size_t rukb = ((size_t)(b * NHEAD + h)) * TDIM;
    int i = tid >> 2, jq = tid & 3;

    float S[16];
#pragma unroll
    for (int q = 0; q < 16; q++) S[q] = 0.f;

    wkv_issue(0, rs[0], ks[0], vs[0], ws[0], rp, kp, vp, wp_, base, tid);

#pragma unroll 1
    for (int ci = 0; ci < TDIM / 8; ci++) {
        int buf = ci & 1;
        asm volatile("cp.async.wait_group 0;" ::: "memory");
        __syncthreads();
        if (ci + 1 < TDIM / 8) {
            int nb = buf ^ 1;
            wkv_issue(ci + 1, rs[nb], ks[nb], vs[nb], ws[nb], rp, kp, vp, wp_, base, tid);
        }
        float4 ruk0 = *(const float4*)(rukp + rukb + ci * 8);
        float4 ruk1 = *(const float4*)(rukp + rukb + ci * 8 + 4);
        float rukv[8] = {ruk0.x, ruk0.y, ruk0.z, ruk0.w, ruk1.x, ruk1.y, ruk1.z, ruk1.w};
#pragma unroll 1
        for (int tc = 0; tc < 8; tc++) {
            float vi = vs[buf][tc * 64 + i];
            const float4* r4 = (const float4*)&rs[buf][tc * 64 + jq * 16];
            const float4* k4 = (const float4*)&ks[buf][tc * 64 + jq * 16];
            const float4* w4 = (const float4*)&ws[buf][tc * 64 + jq * 16];
            float yps = 0.f;
#pragma unroll
            for (int q = 0; q < 4; q++) {
                float4 rv = r4[q], kv = k4[q], wv = w4[q];
                yps += rv.x * S[q * 4 + 0]; S[q * 4 + 0] = wv.x * S[q * 4 + 0] + kv.x * vi;
                yps += rv.y * S[q * 4 + 1]; S[q * 4 + 1] = wv.y * S[q * 4 + 1] + kv.y * vi;
                yps += rv.z * S[q * 4 + 2]; S[q * 4 + 2] = wv.z * S[q * 4 + 2] + kv.z * vi;
                yps += rv.w * S[q * 4 + 3]; S[q * 4 + 3] = wv.w * S[q * 4 + 3] + kv.w * vi;
            }
            yps += __shfl_xor_sync(0xffffffffu, yps, 1);
            yps += __shfl_xor_sync(0xffffffffu, yps, 2);
            if (jq == 0)
                yp[base + (size_t)(ci * 8 + tc) * CDIM + i] = yps + vi * rukv[tc];
        }
    }
}

// ---------------- K5: per-head GroupNorm * g ----------------
__global__ void gn_mul_kernel(const float* __restrict__ y,
                              const float* __restrict__ lw, const float* __restrict__ lb,
                              const float* __restrict__ g, float* __restrict__ out)
{
    int row = blockIdx.x;
    int warp = threadIdx.x >> 5, lane = threadIdx.x & 31;
    size_t o = (size_t)row * CDIM + warp * HS;
    float v0 = y[o + lane], v1 = y[o + 32 + lane];
    float s = v0 + v1, ss = v0 * v0 + v1 * v1;
#pragma unroll
    for (int off = 16; off; off >>= 1) {
        s  += __shfl_xor_sync(0xffffffffu, s,  off);
        ss += __shfl_xor_sync(0xffffffffu, ss, off);
    }
    float mean = s * (1.f / HS);
    float var  = ss * (1.f / HS) - mean * mean;
    float inv  = rsqrtf(var + 1e-5f);
    int c0 = warp * HS + lane, c1 = c0 + 32;
    float n0 = (v0 - mean) * inv * lw[c0] + lb[c0];
    float n1 = (v1 - mean) * inv * lw[c1] + lb[c1];
    out[o + lane]      = tf32r(n0 * g[o + lane]);
    out[o + 32 + lane] = tf32r(n1 * g[o + 32 + lane]);
}

// ---------------- launcher ----------------
extern "C" void kernel_launch(void* const* d_in, const int* in_sizes, int n_in,
                              void* d_out, int out_size)
{
    const float* x          = (const float*)d_in[0];
    const float* W_r        = (const float*)d_in[1];
    const float* W_k        = (const float*)d_in[2];
    const float* W_v        = (const float*)d_in[3];
    const float* W_g        = (const float*)d_in[4];
    const float* W_o        = (const float*)d_in[5];
    const float* maa_x      = (const float*)d_in[6];
    const float* maa_w      = (const float*)d_in[7];
    const float* maa_k      = (const float*)d_in[8];
    const float* maa_v      = (const float*)d_in[9];
    const float* maa_r      = (const float*)d_in[10];
    const float* maa_g      = (const float*)d_in[11];
    const float* maa_w1     = (const float*)d_in[12];
    const float* maa_w2     = (const float*)d_in[13];
    const float* time_decay = (const float*)d_in[14];
    const float* dec_w1     = (const float*)d_in[15];
    const float* dec_w2     = (const float*)d_in[16];
    const float* faaaa      = (const float*)d_in[17];
    const float* ln_w       = (const float*)d_in[18];
    const float* ln_b       = (const float*)d_in[19];
    float* out = (float*)d_out;

    float *xx, *xxx, *tb, *xw, *xk, *xv, *xr, *xg, *rb, *kb, *vb, *gb, *h1, *wb, *yb, *yg, *rukb, *Wc, *Wt, *Wm;
    cudaGetSymbolAddress((void**)&xx,   g_xx);
    cudaGetSymbolAddress((void**)&xxx,  g_xxx);
    cudaGetSymbolAddress((void**)&tb,   g_t);
    cudaGetSymbolAddress((void**)&xw,   g_xw);
    cudaGetSymbolAddress((void**)&xk,   g_xk);
    cudaGetSymbolAddress((void**)&xv,   g_xv);
    cudaGetSymbolAddress((void**)&xr,   g_xr);
    cudaGetSymbolAddress((void**)&xg,   g_xg);
    cudaGetSymbolAddress((void**)&rb,   g_r);
    cudaGetSymbolAddress((void**)&kb,   g_k);
    cudaGetSymbolAddress((void**)&vb,   g_v);
    cudaGetSymbolAddress((void**)&gb,   g_g);
    cudaGetSymbolAddress((void**)&h1,   g_h1);
    cudaGetSymbolAddress((void**)&wb,   g_w);
    cudaGetSymbolAddress((void**)&yb,   g_y);
    cudaGetSymbolAddress((void**)&yg,   g_yg);
    cudaGetSymbolAddress((void**)&rukb, g_ruk);
    cudaGetSymbolAddress((void**)&Wc,   g_Wc);
    cudaGetSymbolAddress((void**)&Wt,   g_Wt);
    cudaGetSymbolAddress((void**)&Wm,   g_Wm);

    const int NW = CDIM * CDIM;
    float* Wr_c = Wc + 0 * NW;
    float* Wk_c = Wc + 1 * NW;
    float* Wv_c = Wc + 2 * NW;
    float* Wg_c = Wc + 3 * NW;
    float* Wo_c = Wc + 4 * NW;
    float* W1t  = Wt;
    float* D1t  = Wt + 160 * CDIM;
    float* D2t  = Wt + 160 * CDIM + 64 * CDIM;

    cudaFuncSetAttribute(gemm_tf32_kernel<0>, cudaFuncAttributeMaxDynamicSharedMemorySize, GT_SMEM);
    cudaFuncSetAttribute(gemm_tf32_batch5_kernel, cudaFuncAttributeMaxDynamicSharedMemorySize, GT_SMEM);
    cudaFuncSetAttribute(gemm_tf32_m64_kernel<4>, cudaFuncAttributeMaxDynamicSharedMemorySize, M64_SMEM);
    cudaFuncSetAttribute(mix5g_kernel, cudaFuncAttributeMaxDynamicSharedMemorySize, M5_SMEM);

    prep_shift_kernel<<<(PRE5 + 255) / 256, 256>>>(W_r, W_k, W_v, W_g, W_o,          // 1
        maa_w1, dec_w1, dec_w2, maa_w2, Wc, Wt, Wm, x, maa_x, xx, xxx);
    {                                                                                 // 2
        dim3 grid(2, NR / 64);
        gemm_tf32_m64_kernel<4><<<grid, 256, M64_SMEM>>>(xxx, W1t, tb, 160, CDIM, nullptr);
    }
    {                                                                                 // 3
        dim3 grid(CDIM / 64, NR / 128);
        mix5g_kernel<<<grid, 256, M5_SMEM>>>(tb, Wm, x, xx,
            maa_w, maa_k, maa_v, maa_r, maa_g, xw, xk, xv, xr, xg);
    }
    {                                                                                 // 4 <- profiled
        dim3 grid(1, NR / 64);
        gemm_tf32_m64_kernel<4><<<grid, 256, M64_SMEM>>>(xw, D1t, h1, 64, CDIM, nullptr);
    }
    {                                                                                 // 5
        dim3 grid(6, NR / 128, 5);
        gemm_tf32_batch5_kernel<<<grid, 256, GT_SMEM>>>(
            xr, xk, xv, xg, h1, Wr_c, Wk_c, Wv_c, Wg_c, D2t,
            rb, kb, vb, gb, wb, time_decay);
    }
    ruk_kernel<<<(NR * NHEAD * 32 + 255) / 256, 256>>>(rb, kb, faaaa, rukb);          // 6
    wkv6_kernel<<<8 * NHEAD, 256>>>(rb, kb, vb, wb, rukb, yb);                        // 7
    gn_mul_kernel<<<NR, 384>>>(yb, ln_w, ln_b, gb, yg);                               // 8
    {                                                                                 // 9
        dim3 gcc(6, NR / 128);
        gemm_tf32_kernel<0><<<gcc, 256, GT_SMEM>>>(yg, Wo_c, out, CDIM, CDIM, nullptr);
    }
}